// round 11
// baseline (speedup 1.0000x reference)
#include <cuda_runtime.h>
#include <cuda_fp16.h>
#include <cstdint>

#define H_ 512
#define W_ 512
#define C_ 64
#define WM_ 128
#define G8_ 8                       // half8 groups per pixel (C=64 -> 8 groups)
#define C4_ 16                      // float4 per pixel
#define HWG (H_*W_*G8_)             // uint4 elements per z component plane
#define HWC4 (H_*W_*C4_)
#define LMBDA 0.1f
#define INV_LMBDA 10.0f
#define TAU 0.1f

// ---------------- scratch (static device globals; no allocations) ----------
static __device__ uint4  g_zA[2*HWG];       // z ping (half): [comp][h][w][g]
static __device__ uint4  g_zB[2*HWG];       // z pong
static __device__ float4 g_X [HWC4];        // X = U - lambda*grad_f(U)   (fp32)
static __device__ float4 g_P [HWC4];        // P = lambda*(Y_H@B_t + R^T@Y_M)
static __device__ uint4  g_Xh[HWG];         // 10*X in half8 (stencil operand)
static __device__ uint4  g_Ph[HWG];         // 10*P in half8
static __device__ float  g_G [W_*W_];       // G = R^T @ R  (512x512)
static __device__ float  g_M1[C_*C_];       // M1 = B @ B_t
static __device__ float  g_Rt[W_*WM_];      // R^T
static __device__ float  g_ssA[4*H_];       // wide partials ping [chunk][comp][h]
static __device__ float  g_ssB[4*H_];       // wide partials pong

// ---------------- half8 (H8) utilities --------------------------------------
struct H8 { __half2 h[4]; };

__device__ __forceinline__ __half2 u2h(unsigned u){
  __half2 r; *reinterpret_cast<unsigned*>(&r) = u; return r;
}
__device__ __forceinline__ unsigned h2u(__half2 h){
  return *reinterpret_cast<unsigned*>(&h);
}
__device__ __forceinline__ H8 ld8h(const uint4* __restrict__ p, int idx){
  const uint4 v = p[idx];
  H8 r; r.h[0]=u2h(v.x); r.h[1]=u2h(v.y); r.h[2]=u2h(v.z); r.h[3]=u2h(v.w);
  return r;
}
__device__ __forceinline__ void st8h(uint4* __restrict__ p, int idx, const H8& r){
  p[idx] = make_uint4(h2u(r.h[0]), h2u(r.h[1]), h2u(r.h[2]), h2u(r.h[3]));
}
__device__ __forceinline__ H8 h8sub(H8 a, H8 b){ H8 r;
#pragma unroll
  for (int i=0;i<4;++i) r.h[i]=__hsub2(a.h[i],b.h[i]); return r; }
__device__ __forceinline__ H8 h8neg(H8 a){ H8 r;
#pragma unroll
  for (int i=0;i<4;++i) r.h[i]=__hneg2(a.h[i]); return r; }

// dz components (Chambolle adjoint), half arithmetic
__device__ __forceinline__ H8 dz1(const uint4* __restrict__ z1, int h, int w, int g){
  if (h == 0)     return ld8h(z1, w*G8_ + g);
  if (h == H_-1)  return h8neg(ld8h(z1, ((H_-2)*W_ + w)*G8_ + g));
  return h8sub(ld8h(z1, (h*W_ + w)*G8_ + g), ld8h(z1, ((h-1)*W_ + w)*G8_ + g));
}
__device__ __forceinline__ H8 dz2(const uint4* __restrict__ z2, int h, int w, int g){
  if (w == 0)     return ld8h(z2, (h*W_)*G8_ + g);
  if (w == W_-1)  return h8neg(ld8h(z2, (h*W_ + (W_-2))*G8_ + g));
  return h8sub(ld8h(z2, (h*W_ + w)*G8_ + g), ld8h(z2, (h*W_ + (w-1))*G8_ + g));
}

// d = s1*dz1 + s2*dz2 + Xh (Xh pre-scaled by 1/lambda)
__device__ __forceinline__ H8 dcalc(const uint4* __restrict__ z1,
                                    const uint4* __restrict__ z2,
                                    const uint4* __restrict__ Xh,
                                    int h, int w, int g, __half2 s1h, __half2 s2h){
  const H8 a = dz1(z1, h, w, g);
  const H8 b = dz2(z2, h, w, g);
  const H8 x = ld8h(Xh, (h*W_ + w)*G8_ + g);
  H8 d;
#pragma unroll
  for (int i=0;i<4;++i)
    d.h[i] = __hfma2(s1h, a.h[i], __hfma2(s2h, b.h[i], x.h[i]));
  return d;
}
// ONES variant: z == 1 -> dz terms are edge constants
__device__ __forceinline__ H8 dcalc1(const uint4* __restrict__ Xh, int h, int w, int g){
  const float a = (h==0)?1.f:((h==H_-1)?-1.f:0.f);
  const float b = (w==0)?1.f:((w==W_-1)?-1.f:0.f);
  const __half2 e = __float2half2_rn(a + b);
  const H8 x = ld8h(Xh, (h*W_ + w)*G8_ + g);
  H8 d;
#pragma unroll
  for (int i=0;i<4;++i) d.h[i] = __hadd2(x.h[i], e);
  return d;
}

// ---------------- fp32 helpers for final_div --------------------------------
struct F8 { float a[8]; };
__device__ __forceinline__ F8 h8f(const H8& x){
  F8 r;
#pragma unroll
  for (int i=0;i<4;++i){
    const float2 f = __half22float2(x.h[i]);
    r.a[2*i] = f.x; r.a[2*i+1] = f.y;
  }
  return r;
}

// ---------------- inline projection scale (wide partial layout) -------------
// ss layout: [0,H) c0/comp1, [H,2H) c0/comp2, [2H,3H) c1/comp1, [3H,4H) c1/comp2
__device__ __forceinline__ void get_scales(const float* __restrict__ ss,
                                           float& s1, float& s2){
  __shared__ float gs1[256], gs2[256];
  const int tid = threadIdx.x;
  float v1 = 0.f, v2 = 0.f;
  for (int h = tid; h < H_; h += 256){
    v1 += sqrtf(ss[h]       + ss[2*H_ + h]);
    v2 += sqrtf(ss[H_ + h]  + ss[3*H_ + h]);
  }
  gs1[tid] = v1; gs2[tid] = v2;
  __syncthreads();
  for (int s = 128; s > 0; s >>= 1){
    if (tid < s){ gs1[tid] += gs1[tid+s]; gs2[tid] += gs2[tid+s]; }
    __syncthreads();
  }
  const float n1 = gs1[0], n2 = gs2[0];
  s1 = (n1 > 1.f) ? (1.f/n1) : 1.f;
  s2 = (n2 > 1.f) ? (1.f/n2) : 1.f;
  __syncthreads();
}

// ---------------- fused dual iteration (half2 math, d-carry along w) --------
// grid (2, H), 256 threads. Thread (tid): g = tid&7, walks 8 consecutive w.
// d(h,w+1) computed for de is carried in registers as next iteration's d00.
template<bool ONES>
__global__ __launch_bounds__(256)
void inner_step(const uint4* __restrict__ zin, uint4* __restrict__ zout,
                const uint4* __restrict__ Xh, const float* __restrict__ ssin,
                float* __restrict__ ssout)
{
  const int h   = blockIdx.y;
  const int w0  = blockIdx.x << 8;
  const int tid = threadIdx.x;
  const uint4* __restrict__ z1 = zin;
  const uint4* __restrict__ z2 = zin + HWG;
  float s1 = 1.f, s2 = 1.f;
  if (!ONES) get_scales(ssin, s1, s2);
  const __half2 s1h = __float2half2_rn(s1);
  const __half2 s2h = __float2half2_rn(s2);
  const __half2 tth = __float2half2_rn(2.f * TAU);
  const __half2 one = __float2half2_rn(1.f);
  float acc1 = 0.f, acc2 = 0.f;

  const int g = tid & 7;
  const int wstart = w0 + ((tid >> 3) << 3);

  // prologue: D = d(h, wstart)
  H8 D = ONES ? dcalc1(Xh, h, wstart, g)
              : dcalc(z1, z2, Xh, h, wstart, g, s1h, s2h);

#pragma unroll 1
  for (int q = 0; q < 8; ++q){
    const int w = wstart + q;
    const int idx = (h*W_ + w)*G8_ + g;

    const H8 d00 = D;
    H8 z1c, z2c;
    if (ONES){
#pragma unroll
      for (int i=0;i<4;++i){ z1c.h[i] = one; z2c.h[i] = one; }
    } else {
      const H8 za = ld8h(z1, idx), zb = ld8h(z2, idx);
#pragma unroll
      for (int i=0;i<4;++i){
        z1c.h[i] = __hmul2(s1h, za.h[i]);
        z2c.h[i] = __hmul2(s2h, zb.h[i]);
      }
    }

    H8 w1o = z1c, w2o = z2c;
    if (h < H_-1){
      const H8 dn = ONES ? dcalc1(Xh, h+1, w, g)
                         : dcalc(z1, z2, Xh, h+1, w, g, s1h, s2h);
#pragma unroll
      for (int i=0;i<4;++i)
        w1o.h[i] = __hfma2(tth, __hsub2(dn.h[i], d00.h[i]), z1c.h[i]);
    }
    if (w < W_-1){
      const H8 de = ONES ? dcalc1(Xh, h, w+1, g)
                         : dcalc(z1, z2, Xh, h, w+1, g, s1h, s2h);
#pragma unroll
      for (int i=0;i<4;++i)
        w2o.h[i] = __hfma2(tth, __hsub2(de.h[i], d00.h[i]), z2c.h[i]);
      D = de;                                  // carry: d00 of next q
    }

    st8h(zout, idx, w1o);
    st8h(zout + HWG, idx, w2o);
#pragma unroll
    for (int i=0;i<4;++i){
      const float2 f1 = __half22float2(w1o.h[i]);
      const float2 f2 = __half22float2(w2o.h[i]);
      acc1 += f1.x*f1.x + f1.y*f1.y;
      acc2 += f2.x*f2.x + f2.y*f2.y;
    }
  }

  __shared__ float sm1[256], sm2[256];
  sm1[tid] = acc1; sm2[tid] = acc2;
  __syncthreads();
  for (int s = 128; s > 0; s >>= 1){
    if (tid < s){ sm1[tid] += sm1[tid+s]; sm2[tid] += sm2[tid+s]; }
    __syncthreads();
  }
  if (tid == 0){
    const int base = blockIdx.x ? 2*H_ : 0;   // disjoint slots per chunk
    ssout[base + h]       = sm1[0];
    ssout[base + H_ + h]  = sm2[0];
  }
}

// proxg output: U = X + LMBDA * div(s .* z)   (fp32 base, fp32 epilogue)
__global__ __launch_bounds__(256)
void final_div(const uint4* __restrict__ zin, const float4* __restrict__ Xp,
               const float* __restrict__ ssin, float4* __restrict__ U)
{
  const int h   = blockIdx.y;
  const int w0  = blockIdx.x << 8;
  const int tid = threadIdx.x;
  const uint4* __restrict__ z1 = zin;
  const uint4* __restrict__ z2 = zin + HWG;
  float s1, s2;
  get_scales(ssin, s1, s2);
#pragma unroll 1
  for (int p = 0; p < 8; ++p){
    const int flat = (p << 8) + tid;
    const int w  = w0 + (flat >> 3);
    const int g  = flat & 7;
    const F8 a = h8f(dz1(z1, h, w, g));
    const F8 b = h8f(dz2(z2, h, w, g));
    const int i4 = (h*W_ + w)*C4_ + 2*g;
    const float4 xp = Xp[i4], xq = Xp[i4+1];
    const float xv[8] = {xp.x,xp.y,xp.z,xp.w, xq.x,xq.y,xq.z,xq.w};
    float r[8];
#pragma unroll
    for (int i = 0; i < 8; ++i)
      r[i] = fmaf(LMBDA, fmaf(s1, a.a[i], s2*b.a[i]), xv[i]);
    U[i4]   = make_float4(r[0], r[1], r[2], r[3]);
    U[i4+1] = make_float4(r[4], r[5], r[6], r[7]);
  }
}

// ---------------- fp16 tensor-core GEMM (2-term hi/lo split) -----------------
__device__ __forceinline__ void mma_f16(float (&c)[4], const uint32_t* a,
                                        const uint32_t* b){
  asm volatile(
    "mma.sync.aligned.m16n8k16.row.col.f32.f16.f16.f32 "
    "{%0,%1,%2,%3}, {%4,%5,%6,%7}, {%8,%9}, {%0,%1,%2,%3};"
    : "+f"(c[0]), "+f"(c[1]), "+f"(c[2]), "+f"(c[3])
    : "r"(a[0]), "r"(a[1]), "r"(a[2]), "r"(a[3]), "r"(b[0]), "r"(b[1]));
}

#define SAH 20                     // A smem stride (b32 units; 16 used + 4 pad)
#define SBH 20                     // B smem stride
#define SMEM_TC ((128*SAH + 64*SBH*2)*4)   // 20.5 KB

// out[h][m0:m0+128, 0:64] = cU*Uin + cMM*( [do_p1] Uin@N1  +  A2@Bin[h] ) + cP*Pb
// If outh != nullptr, also writes INV_LMBDA*result to the half8 buffer.
__global__ __launch_bounds__(256)
void gemm_tc(float* __restrict__ out, int out_h, __half* __restrict__ outh,
             const float* __restrict__ Uin,
             const float* __restrict__ N1,
             const float* __restrict__ A2,
             const float* __restrict__ Bin, int bin_h,
             const float* __restrict__ Pb,
             int K2, int do_p1, float cU, float cMM, float cP)
{
  extern __shared__ unsigned smemU[];
  unsigned* Ah = smemU;             // [128][SAH]  A hi, packed half2 (k pairs)
  unsigned* Bh = Ah + 128*SAH;      // [64][SBH]   B hi, transposed packed
  unsigned* Bl = Bh + 64*SBH;       // [64][SBH]   B lo

  const int h   = blockIdx.y;
  const int m0  = blockIdx.x << 7;
  const int tid = threadIdx.x;
  const int lane = tid & 31, wid = tid >> 5;
  const int wm = wid & 3, wn = wid >> 2;      // 4 x 2 warps over (128m, 64n)
  const int gid = lane >> 2, t4 = lane & 3;

  float acc[2][4][4];
#pragma unroll
  for (int i = 0; i < 2; ++i)
#pragma unroll
    for (int j = 0; j < 4; ++j)
#pragma unroll
      for (int q = 0; q < 4; ++q) acc[i][j][q] = 0.f;

  for (int ph = 0; ph < 2; ++ph){
    const float* Ag; int lda; const float* Bg; int Kp;
    if (ph == 0){
      if (!do_p1) continue;
      Ag = Uin + (size_t)h*32768 + (size_t)m0*64; lda = 64; Bg = N1; Kp = 64;
    } else {
      Ag = A2 + (size_t)m0*K2; lda = K2; Bg = Bin + (size_t)h*bin_h; Kp = K2;
    }
    for (int k0 = 0; k0 < Kp; k0 += 32){
      __syncthreads();
      // fill A chunk 128x32: hi only, packed half2 by k-pairs
      {
        const int row0 = tid >> 3;            // 0..31
        const int k4   = (tid & 7) << 2;      // 0,4,..,28
#pragma unroll
        for (int r = 0; r < 4; ++r){
          const int row = row0 + 32*r;
          const float4 v = *(const float4*)(Ag + (size_t)row*lda + k0 + k4);
          Ah[row*SAH + (k4>>1)]     = h2u(__floats2half2_rn(v.x, v.y));
          Ah[row*SAH + (k4>>1) + 1] = h2u(__floats2half2_rn(v.z, v.w));
        }
      }
      // fill B chunk 32x64: transpose to [n][k2], hi/lo split, packed half2
      {
        const int k2 = tid & 15;              // k-pair index 0..15
        const int n4 = (tid >> 4) << 2;       // 0,4,..,60
        const float* B0 = Bg + (size_t)(k0 + 2*k2)*64 + n4;
        const float4 va = *(const float4*)B0;        // k even row
        const float4 vb = *(const float4*)(B0 + 64); // k odd row
        const float av[4] = {va.x, va.y, va.z, va.w};
        const float bv[4] = {vb.x, vb.y, vb.z, vb.w};
#pragma unroll
        for (int j = 0; j < 4; ++j){
          const __half ha = __float2half_rn(av[j]);
          const __half hb = __float2half_rn(bv[j]);
          const __half la = __float2half_rn(av[j] - __half2float(ha));
          const __half lb = __float2half_rn(bv[j] - __half2float(hb));
          Bh[(n4+j)*SBH + k2] = h2u(__halves2half2(ha, hb));
          Bl[(n4+j)*SBH + k2] = h2u(__halves2half2(la, lb));
        }
      }
      __syncthreads();
#pragma unroll
      for (int kf = 0; kf < 2; ++kf){         // two k16 fragments per chunk
        const int base = kf*8;
        uint32_t ah[2][4];
#pragma unroll
        for (int fm = 0; fm < 2; ++fm){
          const int r0 = wm*32 + fm*16 + gid;
          ah[fm][0] = Ah[r0*SAH + base + t4];
          ah[fm][1] = Ah[(r0+8)*SAH + base + t4];
          ah[fm][2] = Ah[r0*SAH + base + t4 + 4];
          ah[fm][3] = Ah[(r0+8)*SAH + base + t4 + 4];
        }
        uint32_t bhv[4][2], blv[4][2];
#pragma unroll
        for (int fn = 0; fn < 4; ++fn){
          const int n = wn*32 + fn*8 + gid;
          bhv[fn][0] = Bh[n*SBH + base + t4];
          bhv[fn][1] = Bh[n*SBH + base + t4 + 4];
          blv[fn][0] = Bl[n*SBH + base + t4];
          blv[fn][1] = Bl[n*SBH + base + t4 + 4];
        }
#pragma unroll
        for (int fm = 0; fm < 2; ++fm)
#pragma unroll
          for (int fn = 0; fn < 4; ++fn){
            mma_f16(acc[fm][fn], ah[fm], bhv[fn]);   // hi*hi
            mma_f16(acc[fm][fn], ah[fm], blv[fn]);   // hi*lo
          }
      }
    }
  }

  // epilogue
  float* Oh = out + (size_t)h*out_h;
  __half* Ohh = outh ? (outh + (size_t)h*out_h) : nullptr;
  const float* Uh = Uin + (size_t)h*32768;
  const float* Ph = Pb  + (size_t)h*32768;
#pragma unroll
  for (int fm = 0; fm < 2; ++fm){
#pragma unroll
    for (int fn = 0; fn < 4; ++fn){
      const int r0 = m0 + wm*32 + fm*16 + gid;
      const int c0 = wn*32 + fn*8 + 2*t4;
#pragma unroll
      for (int half = 0; half < 2; ++half){
        const int r = r0 + 8*half;
        float v0 = cMM * acc[fm][fn][2*half];
        float v1 = cMM * acc[fm][fn][2*half + 1];
        if (cU != 0.f){
          const float2 u = *(const float2*)(Uh + (size_t)r*64 + c0);
          v0 += cU*u.x; v1 += cU*u.y;
        }
        if (cP != 0.f){
          const float2 pv = *(const float2*)(Ph + (size_t)r*64 + c0);
          v0 += cP*pv.x; v1 += cP*pv.y;
        }
        *(float2*)(Oh + (size_t)r*64 + c0) = make_float2(v0, v1);
        if (Ohh)
          *reinterpret_cast<__half2*>(Ohh + (size_t)r*64 + c0) =
            __floats2half2_rn(INV_LMBDA*v0, INV_LMBDA*v1);
      }
    }
  }
}

// G = R^T @ R : G[m][n] = sum_k R[k][m]*R[k][n]. One-time, fp32 SIMT tiled.
__global__ __launch_bounds__(256)
void gemm_G(float* __restrict__ G, const float* __restrict__ R)
{
  const int mt = (blockIdx.x & 7) << 6;
  const int nt = (blockIdx.x >> 3) << 6;
  __shared__ float Rm[32][68], Rn[32][68];
  const int tid = threadIdx.x, tx = tid & 15, ty = tid >> 4;
  float acc[4][4] = {};
  for (int k0 = 0; k0 < 128; k0 += 32){
    for (int i = tid; i < 32*64; i += 256){
      const int k = i >> 6, c = i & 63;
      Rm[k][c] = R[(k0+k)*512 + mt + c];
      Rn[k][c] = R[(k0+k)*512 + nt + c];
    }
    __syncthreads();
#pragma unroll
    for (int kk = 0; kk < 32; ++kk){
      float a[4], b[4];
#pragma unroll
      for (int i=0;i<4;++i) a[i] = Rm[kk][ty + 16*i];
#pragma unroll
      for (int j=0;j<4;++j) b[j] = Rn[kk][tx + 16*j];
#pragma unroll
      for (int i=0;i<4;++i)
#pragma unroll
        for (int j=0;j<4;++j) acc[i][j] += a[i]*b[j];
    }
    __syncthreads();
  }
#pragma unroll
  for (int i=0;i<4;++i)
#pragma unroll
    for (int j=0;j<4;++j)
      G[(size_t)(mt + ty + 16*i)*512 + nt + tx + 16*j] = acc[i][j];
}

__global__ void transpose_R(float* __restrict__ Rt, const float* __restrict__ R)
{
  const int i = blockIdx.x*256 + threadIdx.x;
  if (i < W_*WM_){
    const int w = i / WM_, m = i % WM_;
    Rt[i] = R[m*W_ + w];
  }
}

__global__ void compute_M1(float* __restrict__ M1, const float* __restrict__ B,
                           const float* __restrict__ Bt)
{
  const int i = blockIdx.x*256 + threadIdx.x;
  if (i < C_*C_){
    const int m = i >> 6, n = i & 63;
    float s = 0.f;
#pragma unroll 8
    for (int k = 0; k < C_; ++k) s += B[m*C_ + k]*Bt[k*C_ + n];
    M1[i] = s;
  }
}

// ---------------- driver ----------------------------------------------------
extern "C" void kernel_launch(void* const* d_in, const int* in_sizes, int n_in,
                              void* d_out, int out_size)
{
  const float* Y_H = (const float*)d_in[0];
  const float* Y_M = (const float*)d_in[1];
  const float* B   = (const float*)d_in[2];
  const float* B_t = (const float*)d_in[3];
  const float* R   = (const float*)d_in[4];
  float* U = (float*)d_out;

  uint4 *zA, *zB, *Xh, *Ph;
  float4 *X, *P;
  float *G, *M1, *Rt, *ssA, *ssB;
  cudaGetSymbolAddress((void**)&zA,  g_zA);
  cudaGetSymbolAddress((void**)&zB,  g_zB);
  cudaGetSymbolAddress((void**)&X,   g_X);
  cudaGetSymbolAddress((void**)&P,   g_P);
  cudaGetSymbolAddress((void**)&Xh,  g_Xh);
  cudaGetSymbolAddress((void**)&Ph,  g_Ph);
  cudaGetSymbolAddress((void**)&G,   g_G);
  cudaGetSymbolAddress((void**)&M1,  g_M1);
  cudaGetSymbolAddress((void**)&Rt,  g_Rt);
  cudaGetSymbolAddress((void**)&ssA, g_ssA);
  cudaGetSymbolAddress((void**)&ssB, g_ssB);

  const dim3 blk2(256);
  const dim3 grd2(2, H_);

  transpose_R<<<(W_*WM_ + 255)/256, 256>>>(Rt, R);
  compute_M1 <<<(C_*C_ + 255)/256, 256>>>(M1, B, B_t);
  gemm_G     <<<64, 256>>>(G, R);
  // P = LMBDA*(Y_H@B_t + Rt@Y_M), plus Ph = 10*P in half
  gemm_tc<<<dim3(4, H_), 256, SMEM_TC>>>((float*)P, 32768, (__half*)Ph,
                                         Y_H, B_t, Rt, Y_M, WM_*C_,
                                         (const float*)P,
                                         WM_, 1, 0.f, LMBDA, 0.f);

  uint4* zbuf[2]  = { zA, zB };
  float* ssbuf[2] = { ssA, ssB };
  for (int it = 0; it < 5; ++it){
    const uint4* Xhp;
    const float4* Xp;
    if (it == 0){
      Xhp = Ph; Xp = P;                         // U = 0 -> X = P exactly
    } else {
      // X = U - LMBDA*(U@M1 + G@U) + P, plus Xh = 10*X in half  (single GEMM)
      gemm_tc<<<dim3(4, H_), 256, SMEM_TC>>>((float*)X, 32768, (__half*)Xh,
                                             U, M1, G, U, 32768,
                                             (const float*)P,
                                             W_, 1, 1.f, -LMBDA, 1.f);
      Xhp = Xh; Xp = X;
    }
    inner_step<true><<<grd2, blk2>>>(zbuf[1], zbuf[0], Xhp, ssbuf[1], ssbuf[0]);
    for (int j = 1; j < 5; ++j){
      inner_step<false><<<grd2, blk2>>>(zbuf[(j-1)&1], zbuf[j&1], Xhp,
                                        ssbuf[(j-1)&1], ssbuf[j&1]);
    }
    final_div<<<grd2, blk2>>>(zbuf[0], Xp, ssbuf[0], (float4*)U);
  }
}

// round 12
// speedup vs baseline: 1.1445x; 1.1445x over previous
#include <cuda_runtime.h>
#include <cuda_fp16.h>
#include <cstdint>

#define H_ 512
#define W_ 512
#define C_ 64
#define WM_ 128
#define G8_ 8                       // half8 groups per pixel (C=64 -> 8 groups)
#define C4_ 16                      // float4 per pixel
#define HWG (H_*W_*G8_)             // uint4 elements per z component plane
#define HWC4 (H_*W_*C4_)
#define LMBDA 0.1f
#define INV_LMBDA 10.0f
#define TAU 0.1f
#define NCTA_STEP 1024u             // inner_step grid = (2, H) = 1024 CTAs

// ---------------- scratch (static device globals; no allocations) ----------
static __device__ uint4  g_zA[2*HWG];       // z ping (half): [comp][h][w][g]
static __device__ uint4  g_zB[2*HWG];       // z pong
static __device__ float4 g_X [HWC4];        // X = U - lambda*grad_f(U)   (fp32)
static __device__ float4 g_P [HWC4];        // P = lambda*(Y_H@B_t + R^T@Y_M)
static __device__ uint4  g_Xh[HWG];         // 10*X in half8 (stencil operand)
static __device__ uint4  g_Ph[HWG];         // 10*P in half8
static __device__ float  g_T [H_*WM_*C_];   // T[h] = R @ U[h]
static __device__ float  g_M1[C_*C_];       // M1 = B @ B_t
static __device__ float  g_Rt[W_*WM_];      // R^T
static __device__ float  g_ss[4*H_];        // wide partials [chunk][comp][h]
static __device__ float  g_sc[2];           // projection scales (s1, s2)
static __device__ unsigned g_cnt;           // arrival counter (self-resetting)

// ---------------- half8 (H8) utilities --------------------------------------
struct H8 { __half2 h[4]; };

__device__ __forceinline__ __half2 u2h(unsigned u){
  __half2 r; *reinterpret_cast<unsigned*>(&r) = u; return r;
}
__device__ __forceinline__ unsigned h2u(__half2 h){
  return *reinterpret_cast<unsigned*>(&h);
}
__device__ __forceinline__ H8 ld8h(const uint4* __restrict__ p, int idx){
  const uint4 v = p[idx];
  H8 r; r.h[0]=u2h(v.x); r.h[1]=u2h(v.y); r.h[2]=u2h(v.z); r.h[3]=u2h(v.w);
  return r;
}
__device__ __forceinline__ void st8h(uint4* __restrict__ p, int idx, const H8& r){
  p[idx] = make_uint4(h2u(r.h[0]), h2u(r.h[1]), h2u(r.h[2]), h2u(r.h[3]));
}
__device__ __forceinline__ H8 h8sub(H8 a, H8 b){ H8 r;
#pragma unroll
  for (int i=0;i<4;++i) r.h[i]=__hsub2(a.h[i],b.h[i]); return r; }
__device__ __forceinline__ H8 h8neg(H8 a){ H8 r;
#pragma unroll
  for (int i=0;i<4;++i) r.h[i]=__hneg2(a.h[i]); return r; }

// dz components (Chambolle adjoint), half arithmetic
__device__ __forceinline__ H8 dz1(const uint4* __restrict__ z1, int h, int w, int g){
  if (h == 0)     return ld8h(z1, w*G8_ + g);
  if (h == H_-1)  return h8neg(ld8h(z1, ((H_-2)*W_ + w)*G8_ + g));
  return h8sub(ld8h(z1, (h*W_ + w)*G8_ + g), ld8h(z1, ((h-1)*W_ + w)*G8_ + g));
}
__device__ __forceinline__ H8 dz2(const uint4* __restrict__ z2, int h, int w, int g){
  if (w == 0)     return ld8h(z2, (h*W_)*G8_ + g);
  if (w == W_-1)  return h8neg(ld8h(z2, (h*W_ + (W_-2))*G8_ + g));
  return h8sub(ld8h(z2, (h*W_ + w)*G8_ + g), ld8h(z2, (h*W_ + (w-1))*G8_ + g));
}

// d = s1*dz1 + s2*dz2 + Xh (Xh pre-scaled by 1/lambda)
__device__ __forceinline__ H8 dcalc(const uint4* __restrict__ z1,
                                    const uint4* __restrict__ z2,
                                    const uint4* __restrict__ Xh,
                                    int h, int w, int g, __half2 s1h, __half2 s2h){
  const H8 a = dz1(z1, h, w, g);
  const H8 b = dz2(z2, h, w, g);
  const H8 x = ld8h(Xh, (h*W_ + w)*G8_ + g);
  H8 d;
#pragma unroll
  for (int i=0;i<4;++i)
    d.h[i] = __hfma2(s1h, a.h[i], __hfma2(s2h, b.h[i], x.h[i]));
  return d;
}
// ONES variant: z == 1 -> dz terms are edge constants
__device__ __forceinline__ H8 dcalc1(const uint4* __restrict__ Xh, int h, int w, int g){
  const float a = (h==0)?1.f:((h==H_-1)?-1.f:0.f);
  const float b = (w==0)?1.f:((w==W_-1)?-1.f:0.f);
  const __half2 e = __float2half2_rn(a + b);
  const H8 x = ld8h(Xh, (h*W_ + w)*G8_ + g);
  H8 d;
#pragma unroll
  for (int i=0;i<4;++i) d.h[i] = __hadd2(x.h[i], e);
  return d;
}

// ---------------- fp32 helpers for final_div --------------------------------
struct F8 { float a[8]; };
__device__ __forceinline__ F8 h8f(const H8& x){
  F8 r;
#pragma unroll
  for (int i=0;i<4;++i){
    const float2 f = __half22float2(x.h[i]);
    r.a[2*i] = f.x; r.a[2*i+1] = f.y;
  }
  return r;
}

// ---------------- fused dual iteration (round-10 mapping, half2 math) --------
// grid (2, H), 256 threads; half-row (256 w) per CTA, p-loop strided mapping.
// Tail: each CTA writes its ss partial; the LAST CTA (atomic elect) reduces all
// partials to the 2 projection scales (fixed order -> deterministic) and
// resets the counter (graph-replay safe).
template<bool ONES>
__global__ __launch_bounds__(256)
void inner_step(const uint4* __restrict__ zin, uint4* __restrict__ zout,
                const uint4* __restrict__ Xh, const float* __restrict__ sc_in,
                float* __restrict__ ss, float* __restrict__ sc_out,
                unsigned* __restrict__ cnt)
{
  const int h   = blockIdx.y;
  const int w0  = blockIdx.x << 8;
  const int tid = threadIdx.x;
  const uint4* __restrict__ z1 = zin;
  const uint4* __restrict__ z2 = zin + HWG;
  float s1 = 1.f, s2 = 1.f;
  if (!ONES){ s1 = sc_in[0]; s2 = sc_in[1]; }
  const __half2 s1h = __float2half2_rn(s1);
  const __half2 s2h = __float2half2_rn(s2);
  const __half2 tth = __float2half2_rn(2.f * TAU);
  const __half2 one = __float2half2_rn(1.f);
  const __half2 inv16 = __float2half2_rn(0.0625f);
  __half2 acch1 = __float2half2_rn(0.f);
  __half2 acch2 = __float2half2_rn(0.f);

#pragma unroll 1
  for (int p = 0; p < 8; ++p){
    const int flat = (p << 8) + tid;       // 0..2047
    const int w  = w0 + (flat >> 3);
    const int g  = flat & 7;
    const int idx = (h*W_ + w)*G8_ + g;

    H8 d00, z1c, z2c;
    if (ONES){
      d00 = dcalc1(Xh, h, w, g);
#pragma unroll
      for (int i=0;i<4;++i){ z1c.h[i] = one; z2c.h[i] = one; }
    } else {
      d00 = dcalc(z1, z2, Xh, h, w, g, s1h, s2h);
      const H8 za = ld8h(z1, idx), zb = ld8h(z2, idx);
#pragma unroll
      for (int i=0;i<4;++i){
        z1c.h[i] = __hmul2(s1h, za.h[i]);
        z2c.h[i] = __hmul2(s2h, zb.h[i]);
      }
    }

    H8 w1o = z1c, w2o = z2c;
    if (h < H_-1){
      const H8 dn = ONES ? dcalc1(Xh, h+1, w, g)
                         : dcalc(z1, z2, Xh, h+1, w, g, s1h, s2h);
#pragma unroll
      for (int i=0;i<4;++i)
        w1o.h[i] = __hfma2(tth, __hsub2(dn.h[i], d00.h[i]), z1c.h[i]);
    }
    if (w < W_-1){
      const H8 de = ONES ? dcalc1(Xh, h, w+1, g)
                         : dcalc(z1, z2, Xh, h, w+1, g, s1h, s2h);
#pragma unroll
      for (int i=0;i<4;++i)
        w2o.h[i] = __hfma2(tth, __hsub2(de.h[i], d00.h[i]), z2c.h[i]);
    }

    st8h(zout, idx, w1o);
    st8h(zout + HWG, idx, w2o);
    // half2 sum-of-squares with 1/16 prescale (rescaled x256 at reduction)
#pragma unroll
    for (int i=0;i<4;++i){
      const __half2 t1 = __hmul2(w1o.h[i], inv16);
      const __half2 t2 = __hmul2(w2o.h[i], inv16);
      acch1 = __hfma2(t1, t1, acch1);
      acch2 = __hfma2(t2, t2, acch2);
    }
  }

  __shared__ float sm1[256], sm2[256];
  __shared__ int elected;
  {
    const float2 f1 = __half22float2(acch1);
    const float2 f2 = __half22float2(acch2);
    sm1[tid] = (f1.x + f1.y) * 256.f;
    sm2[tid] = (f2.x + f2.y) * 256.f;
  }
  __syncthreads();
  for (int s = 128; s > 0; s >>= 1){
    if (tid < s){ sm1[tid] += sm1[tid+s]; sm2[tid] += sm2[tid+s]; }
    __syncthreads();
  }
  if (tid == 0){
    const int base = blockIdx.x ? 2*H_ : 0;   // disjoint slots per chunk
    ss[base + h]       = sm1[0];
    ss[base + H_ + h]  = sm2[0];
    __threadfence();
    const unsigned old = atomicAdd(cnt, 1u);
    elected = (old == NCTA_STEP - 1u);
  }
  __syncthreads();
  if (elected){
    __threadfence();
    float v1 = 0.f, v2 = 0.f;
    for (int hh = tid; hh < H_; hh += 256){
      v1 += sqrtf(ss[hh]       + ss[2*H_ + hh]);
      v2 += sqrtf(ss[H_ + hh]  + ss[3*H_ + hh]);
    }
    sm1[tid] = v1; sm2[tid] = v2;
    __syncthreads();
    for (int s = 128; s > 0; s >>= 1){
      if (tid < s){ sm1[tid] += sm1[tid+s]; sm2[tid] += sm2[tid+s]; }
      __syncthreads();
    }
    if (tid == 0){
      const float n1 = sm1[0], n2 = sm2[0];
      sc_out[0] = (n1 > 1.f) ? (1.f/n1) : 1.f;
      sc_out[1] = (n2 > 1.f) ? (1.f/n2) : 1.f;
      __threadfence();
      *cnt = 0u;                              // reset for next launch/replay
    }
  }
}

// proxg output: U = X + LMBDA * div(s .* z)   (fp32 base, fp32 epilogue)
__global__ __launch_bounds__(256)
void final_div(const uint4* __restrict__ zin, const float4* __restrict__ Xp,
               const float* __restrict__ sc, float4* __restrict__ U)
{
  const int h   = blockIdx.y;
  const int w0  = blockIdx.x << 8;
  const int tid = threadIdx.x;
  const uint4* __restrict__ z1 = zin;
  const uint4* __restrict__ z2 = zin + HWG;
  const float s1 = sc[0], s2 = sc[1];
#pragma unroll 1
  for (int p = 0; p < 8; ++p){
    const int flat = (p << 8) + tid;
    const int w  = w0 + (flat >> 3);
    const int g  = flat & 7;
    const F8 a = h8f(dz1(z1, h, w, g));
    const F8 b = h8f(dz2(z2, h, w, g));
    const int i4 = (h*W_ + w)*C4_ + 2*g;
    const float4 xp = Xp[i4], xq = Xp[i4+1];
    const float xv[8] = {xp.x,xp.y,xp.z,xp.w, xq.x,xq.y,xq.z,xq.w};
    float r[8];
#pragma unroll
    for (int i = 0; i < 8; ++i)
      r[i] = fmaf(LMBDA, fmaf(s1, a.a[i], s2*b.a[i]), xv[i]);
    U[i4]   = make_float4(r[0], r[1], r[2], r[3]);
    U[i4+1] = make_float4(r[4], r[5], r[6], r[7]);
  }
}

// ---------------- fp16 tensor-core GEMM (2-term hi/lo split) -----------------
__device__ __forceinline__ void mma_f16(float (&c)[4], const uint32_t* a,
                                        const uint32_t* b){
  asm volatile(
    "mma.sync.aligned.m16n8k16.row.col.f32.f16.f16.f32 "
    "{%0,%1,%2,%3}, {%4,%5,%6,%7}, {%8,%9}, {%0,%1,%2,%3};"
    : "+f"(c[0]), "+f"(c[1]), "+f"(c[2]), "+f"(c[3])
    : "r"(a[0]), "r"(a[1]), "r"(a[2]), "r"(a[3]), "r"(b[0]), "r"(b[1]));
}

#define SAH 20                     // A smem stride (b32 units; 16 used + 4 pad)
#define SBH 20                     // B smem stride
#define SMEM_TC ((128*SAH + 64*SBH*2)*4)   // 20.5 KB

// out[h][m0:m0+128, 0:64] = cU*Uin + cMM*( [do_p1] Uin@N1  +  A2@Bin[h] ) + cP*Pb
// If outh != nullptr, also writes INV_LMBDA*result to the half8 buffer.
__global__ __launch_bounds__(256)
void gemm_tc(float* __restrict__ out, int out_h, __half* __restrict__ outh,
             const float* __restrict__ Uin,
             const float* __restrict__ N1,
             const float* __restrict__ A2,
             const float* __restrict__ Bin, int bin_h,
             const float* __restrict__ Pb,
             int K2, int do_p1, float cU, float cMM, float cP)
{
  extern __shared__ unsigned smemU[];
  unsigned* Ah = smemU;             // [128][SAH]  A hi, packed half2 (k pairs)
  unsigned* Bh = Ah + 128*SAH;      // [64][SBH]   B hi, transposed packed
  unsigned* Bl = Bh + 64*SBH;       // [64][SBH]   B lo

  const int h   = blockIdx.y;
  const int m0  = blockIdx.x << 7;
  const int tid = threadIdx.x;
  const int lane = tid & 31, wid = tid >> 5;
  const int wm = wid & 3, wn = wid >> 2;      // 4 x 2 warps over (128m, 64n)
  const int gid = lane >> 2, t4 = lane & 3;

  float acc[2][4][4];
#pragma unroll
  for (int i = 0; i < 2; ++i)
#pragma unroll
    for (int j = 0; j < 4; ++j)
#pragma unroll
      for (int q = 0; q < 4; ++q) acc[i][j][q] = 0.f;

  for (int ph = 0; ph < 2; ++ph){
    const float* Ag; int lda; const float* Bg; int Kp;
    if (ph == 0){
      if (!do_p1) continue;
      Ag = Uin + (size_t)h*32768 + (size_t)m0*64; lda = 64; Bg = N1; Kp = 64;
    } else {
      Ag = A2 + (size_t)m0*K2; lda = K2; Bg = Bin + (size_t)h*bin_h; Kp = K2;
    }
    for (int k0 = 0; k0 < Kp; k0 += 32){
      __syncthreads();
      // fill A chunk 128x32: hi only, packed half2 by k-pairs
      {
        const int row0 = tid >> 3;            // 0..31
        const int k4   = (tid & 7) << 2;      // 0,4,..,28
#pragma unroll
        for (int r = 0; r < 4; ++r){
          const int row = row0 + 32*r;
          const float4 v = *(const float4*)(Ag + (size_t)row*lda + k0 + k4);
          Ah[row*SAH + (k4>>1)]     = h2u(__floats2half2_rn(v.x, v.y));
          Ah[row*SAH + (k4>>1) + 1] = h2u(__floats2half2_rn(v.z, v.w));
        }
      }
      // fill B chunk 32x64: transpose to [n][k2], hi/lo split, packed half2
      {
        const int k2 = tid & 15;              // k-pair index 0..15
        const int n4 = (tid >> 4) << 2;       // 0,4,..,60
        const float* B0 = Bg + (size_t)(k0 + 2*k2)*64 + n4;
        const float4 va = *(const float4*)B0;        // k even row
        const float4 vb = *(const float4*)(B0 + 64); // k odd row
        const float av[4] = {va.x, va.y, va.z, va.w};
        const float bv[4] = {vb.x, vb.y, vb.z, vb.w};
#pragma unroll
        for (int j = 0; j < 4; ++j){
          const __half ha = __float2half_rn(av[j]);
          const __half hb = __float2half_rn(bv[j]);
          const __half la = __float2half_rn(av[j] - __half2float(ha));
          const __half lb = __float2half_rn(bv[j] - __half2float(hb));
          Bh[(n4+j)*SBH + k2] = h2u(__halves2half2(ha, hb));
          Bl[(n4+j)*SBH + k2] = h2u(__halves2half2(la, lb));
        }
      }
      __syncthreads();
#pragma unroll
      for (int kf = 0; kf < 2; ++kf){         // two k16 fragments per chunk
        const int base = kf*8;
        uint32_t ah[2][4];
#pragma unroll
        for (int fm = 0; fm < 2; ++fm){
          const int r0 = wm*32 + fm*16 + gid;
          ah[fm][0] = Ah[r0*SAH + base + t4];
          ah[fm][1] = Ah[(r0+8)*SAH + base + t4];
          ah[fm][2] = Ah[r0*SAH + base + t4 + 4];
          ah[fm][3] = Ah[(r0+8)*SAH + base + t4 + 4];
        }
        uint32_t bhv[4][2], blv[4][2];
#pragma unroll
        for (int fn = 0; fn < 4; ++fn){
          const int n = wn*32 + fn*8 + gid;
          bhv[fn][0] = Bh[n*SBH + base + t4];
          bhv[fn][1] = Bh[n*SBH + base + t4 + 4];
          blv[fn][0] = Bl[n*SBH + base + t4];
          blv[fn][1] = Bl[n*SBH + base + t4 + 4];
        }
#pragma unroll
        for (int fm = 0; fm < 2; ++fm)
#pragma unroll
          for (int fn = 0; fn < 4; ++fn){
            mma_f16(acc[fm][fn], ah[fm], bhv[fn]);   // hi*hi
            mma_f16(acc[fm][fn], ah[fm], blv[fn]);   // hi*lo
          }
      }
    }
  }

  // epilogue
  float* Oh = out + (size_t)h*out_h;
  __half* Ohh = outh ? (outh + (size_t)h*out_h) : nullptr;
  const float* Uh = Uin + (size_t)h*32768;
  const float* Ph = Pb  + (size_t)h*32768;
#pragma unroll
  for (int fm = 0; fm < 2; ++fm){
#pragma unroll
    for (int fn = 0; fn < 4; ++fn){
      const int r0 = m0 + wm*32 + fm*16 + gid;
      const int c0 = wn*32 + fn*8 + 2*t4;
#pragma unroll
      for (int half = 0; half < 2; ++half){
        const int r = r0 + 8*half;
        float v0 = cMM * acc[fm][fn][2*half];
        float v1 = cMM * acc[fm][fn][2*half + 1];
        if (cU != 0.f){
          const float2 u = *(const float2*)(Uh + (size_t)r*64 + c0);
          v0 += cU*u.x; v1 += cU*u.y;
        }
        if (cP != 0.f){
          const float2 pv = *(const float2*)(Ph + (size_t)r*64 + c0);
          v0 += cP*pv.x; v1 += cP*pv.y;
        }
        *(float2*)(Oh + (size_t)r*64 + c0) = make_float2(v0, v1);
        if (Ohh)
          *reinterpret_cast<__half2*>(Ohh + (size_t)r*64 + c0) =
            __floats2half2_rn(INV_LMBDA*v0, INV_LMBDA*v1);
      }
    }
  }
}

__global__ void transpose_R(float* __restrict__ Rt, const float* __restrict__ R)
{
  const int i = blockIdx.x*256 + threadIdx.x;
  if (i < W_*WM_){
    const int w = i / WM_, m = i % WM_;
    Rt[i] = R[m*W_ + w];
  }
}

__global__ void compute_M1(float* __restrict__ M1, const float* __restrict__ B,
                           const float* __restrict__ Bt)
{
  const int i = blockIdx.x*256 + threadIdx.x;
  if (i < C_*C_){
    const int m = i >> 6, n = i & 63;
    float s = 0.f;
#pragma unroll 8
    for (int k = 0; k < C_; ++k) s += B[m*C_ + k]*Bt[k*C_ + n];
    M1[i] = s;
  }
}

// ---------------- driver ----------------------------------------------------
extern "C" void kernel_launch(void* const* d_in, const int* in_sizes, int n_in,
                              void* d_out, int out_size)
{
  const float* Y_H = (const float*)d_in[0];
  const float* Y_M = (const float*)d_in[1];
  const float* B   = (const float*)d_in[2];
  const float* B_t = (const float*)d_in[3];
  const float* R   = (const float*)d_in[4];
  float* U = (float*)d_out;

  uint4 *zA, *zB, *Xh, *Ph;
  float4 *X, *P;
  float *T, *M1, *Rt, *ss, *sc;
  unsigned* cnt;
  cudaGetSymbolAddress((void**)&zA,  g_zA);
  cudaGetSymbolAddress((void**)&zB,  g_zB);
  cudaGetSymbolAddress((void**)&X,   g_X);
  cudaGetSymbolAddress((void**)&P,   g_P);
  cudaGetSymbolAddress((void**)&Xh,  g_Xh);
  cudaGetSymbolAddress((void**)&Ph,  g_Ph);
  cudaGetSymbolAddress((void**)&T,   g_T);
  cudaGetSymbolAddress((void**)&M1,  g_M1);
  cudaGetSymbolAddress((void**)&Rt,  g_Rt);
  cudaGetSymbolAddress((void**)&ss,  g_ss);
  cudaGetSymbolAddress((void**)&sc,  g_sc);
  cudaGetSymbolAddress((void**)&cnt, g_cnt);

  const dim3 blk2(256);
  const dim3 grd2(2, H_);

  transpose_R<<<(W_*WM_ + 255)/256, 256>>>(Rt, R);
  compute_M1 <<<(C_*C_ + 255)/256, 256>>>(M1, B, B_t);
  // P = LMBDA*(Y_H@B_t + Rt@Y_M), plus Ph = 10*P in half
  gemm_tc<<<dim3(4, H_), 256, SMEM_TC>>>((float*)P, 32768, (__half*)Ph,
                                         Y_H, B_t, Rt, Y_M, WM_*C_,
                                         (const float*)P,
                                         WM_, 1, 0.f, LMBDA, 0.f);

  uint4* zbuf[2] = { zA, zB };
  for (int it = 0; it < 5; ++it){
    const uint4* Xhp;
    const float4* Xp;
    if (it == 0){
      Xhp = Ph; Xp = P;                         // U = 0 -> X = P exactly
    } else {
      // T[h] = R @ U[h]
      gemm_tc<<<dim3(1, H_), 256, SMEM_TC>>>(T, WM_*C_, (__half*)nullptr,
                                             U, M1, R, U, W_*C_,
                                             (const float*)P,
                                             W_, 0, 0.f, 1.f, 0.f);
      // X = U - LMBDA*(U@M1 + Rt@T) + P, plus Xh = 10*X in half
      gemm_tc<<<dim3(4, H_), 256, SMEM_TC>>>((float*)X, 32768, (__half*)Xh,
                                             U, M1, Rt, T, WM_*C_,
                                             (const float*)P,
                                             WM_, 1, 1.f, -LMBDA, 1.f);
      Xhp = Xh; Xp = X;
    }
    inner_step<true><<<grd2, blk2>>>(zbuf[1], zbuf[0], Xhp, sc, ss, sc, cnt);
    for (int j = 1; j < 5; ++j){
      inner_step<false><<<grd2, blk2>>>(zbuf[(j-1)&1], zbuf[j&1], Xhp,
                                        sc, ss, sc, cnt);
    }
    final_div<<<grd2, blk2>>>(zbuf[0], Xp, sc, (float4*)U);
  }
}

// round 13
// speedup vs baseline: 1.1815x; 1.0323x over previous
#include <cuda_runtime.h>
#include <cuda_fp16.h>
#include <cstdint>

#define H_ 512
#define W_ 512
#define C_ 64
#define WM_ 128
#define G8_ 8                       // half8 groups per pixel (C=64 -> 8 groups)
#define C4_ 16                      // float4 per pixel
#define HWG (H_*W_*G8_)             // uint4 elements per z component plane
#define HWC4 (H_*W_*C4_)
#define LMBDA 0.1f
#define INV_LMBDA 10.0f
#define TAU 0.1f
#define NCTA_STEP 1024u             // inner_step grid = (2, H) = 1024 CTAs

// ---------------- scratch (static device globals; no allocations) ----------
static __device__ uint4  g_zA[2*HWG];       // z ping (half): [comp][h][w][g]
static __device__ uint4  g_zB[2*HWG];       // z pong
static __device__ float4 g_X [HWC4];        // X = U - lambda*grad_f(U)   (fp32)
static __device__ float4 g_P [HWC4];        // P = lambda*(Y_H@B_t + R^T@Y_M)
static __device__ uint4  g_Xh[HWG];         // 10*X in half8 (stencil operand)
static __device__ uint4  g_Ph[HWG];         // 10*P in half8
static __device__ float  g_T [H_*WM_*C_];   // T[h] = R @ U[h]
static __device__ float  g_M1[C_*C_];       // M1 = B @ B_t
static __device__ float  g_Rt[W_*WM_];      // R^T
static __device__ float  g_ss[4*H_];        // wide partials [chunk][comp][h]
static __device__ float  g_sc[2];           // projection scales (s1, s2)
static __device__ unsigned g_cnt;           // arrival counter (self-resetting)

// ---------------- half8 (H8) utilities --------------------------------------
struct H8 { __half2 h[4]; };

__device__ __forceinline__ __half2 u2h(unsigned u){
  __half2 r; *reinterpret_cast<unsigned*>(&r) = u; return r;
}
__device__ __forceinline__ unsigned h2u(__half2 h){
  return *reinterpret_cast<unsigned*>(&h);
}
__device__ __forceinline__ H8 ld8h(const uint4* __restrict__ p, int idx){
  const uint4 v = p[idx];
  H8 r; r.h[0]=u2h(v.x); r.h[1]=u2h(v.y); r.h[2]=u2h(v.z); r.h[3]=u2h(v.w);
  return r;
}
__device__ __forceinline__ void st8h(uint4* __restrict__ p, int idx, const H8& r){
  p[idx] = make_uint4(h2u(r.h[0]), h2u(r.h[1]), h2u(r.h[2]), h2u(r.h[3]));
}
__device__ __forceinline__ H8 h8sub(H8 a, H8 b){ H8 r;
#pragma unroll
  for (int i=0;i<4;++i) r.h[i]=__hsub2(a.h[i],b.h[i]); return r; }
__device__ __forceinline__ H8 h8neg(H8 a){ H8 r;
#pragma unroll
  for (int i=0;i<4;++i) r.h[i]=__hneg2(a.h[i]); return r; }

// dz components (Chambolle adjoint), half arithmetic
__device__ __forceinline__ H8 dz1(const uint4* __restrict__ z1, int h, int w, int g){
  if (h == 0)     return ld8h(z1, w*G8_ + g);
  if (h == H_-1)  return h8neg(ld8h(z1, ((H_-2)*W_ + w)*G8_ + g));
  return h8sub(ld8h(z1, (h*W_ + w)*G8_ + g), ld8h(z1, ((h-1)*W_ + w)*G8_ + g));
}
__device__ __forceinline__ H8 dz2(const uint4* __restrict__ z2, int h, int w, int g){
  if (w == 0)     return ld8h(z2, (h*W_)*G8_ + g);
  if (w == W_-1)  return h8neg(ld8h(z2, (h*W_ + (W_-2))*G8_ + g));
  return h8sub(ld8h(z2, (h*W_ + w)*G8_ + g), ld8h(z2, (h*W_ + (w-1))*G8_ + g));
}

// d = s1*dz1 + s2*dz2 + Xh (Xh pre-scaled by 1/lambda)
__device__ __forceinline__ H8 dcalc(const uint4* __restrict__ z1,
                                    const uint4* __restrict__ z2,
                                    const uint4* __restrict__ Xh,
                                    int h, int w, int g, __half2 s1h, __half2 s2h){
  const H8 a = dz1(z1, h, w, g);
  const H8 b = dz2(z2, h, w, g);
  const H8 x = ld8h(Xh, (h*W_ + w)*G8_ + g);
  H8 d;
#pragma unroll
  for (int i=0;i<4;++i)
    d.h[i] = __hfma2(s1h, a.h[i], __hfma2(s2h, b.h[i], x.h[i]));
  return d;
}
// ONES variant: z == 1 -> dz terms are edge constants
__device__ __forceinline__ H8 dcalc1(const uint4* __restrict__ Xh, int h, int w, int g){
  const float a = (h==0)?1.f:((h==H_-1)?-1.f:0.f);
  const float b = (w==0)?1.f:((w==W_-1)?-1.f:0.f);
  const __half2 e = __float2half2_rn(a + b);
  const H8 x = ld8h(Xh, (h*W_ + w)*G8_ + g);
  H8 d;
#pragma unroll
  for (int i=0;i<4;++i) d.h[i] = __hadd2(x.h[i], e);
  return d;
}

// ---------------- fp32 helpers for final_div --------------------------------
struct F8 { float a[8]; };
__device__ __forceinline__ F8 h8f(const H8& x){
  F8 r;
#pragma unroll
  for (int i=0;i<4;++i){
    const float2 f = __half22float2(x.h[i]);
    r.a[2*i] = f.x; r.a[2*i+1] = f.y;
  }
  return r;
}

// ---------------- fused dual iteration (half2 math, elected-scale tail) ------
// grid (2, H), 256 threads; half-row (256 w) per CTA, p-loop strided mapping.
template<bool ONES>
__global__ __launch_bounds__(256)
void inner_step(const uint4* __restrict__ zin, uint4* __restrict__ zout,
                const uint4* __restrict__ Xh, const float* __restrict__ sc_in,
                float* __restrict__ ss, float* __restrict__ sc_out,
                unsigned* __restrict__ cnt)
{
  const int h   = blockIdx.y;
  const int w0  = blockIdx.x << 8;
  const int tid = threadIdx.x;
  const uint4* __restrict__ z1 = zin;
  const uint4* __restrict__ z2 = zin + HWG;
  float s1 = 1.f, s2 = 1.f;
  if (!ONES){ s1 = sc_in[0]; s2 = sc_in[1]; }
  const __half2 s1h = __float2half2_rn(s1);
  const __half2 s2h = __float2half2_rn(s2);
  const __half2 tth = __float2half2_rn(2.f * TAU);
  const __half2 one = __float2half2_rn(1.f);
  const __half2 inv16 = __float2half2_rn(0.0625f);
  __half2 acch1 = __float2half2_rn(0.f);
  __half2 acch2 = __float2half2_rn(0.f);

#pragma unroll 1
  for (int p = 0; p < 8; ++p){
    const int flat = (p << 8) + tid;       // 0..2047
    const int w  = w0 + (flat >> 3);
    const int g  = flat & 7;
    const int idx = (h*W_ + w)*G8_ + g;

    H8 d00, z1c, z2c;
    if (ONES){
      d00 = dcalc1(Xh, h, w, g);
#pragma unroll
      for (int i=0;i<4;++i){ z1c.h[i] = one; z2c.h[i] = one; }
    } else {
      d00 = dcalc(z1, z2, Xh, h, w, g, s1h, s2h);
      const H8 za = ld8h(z1, idx), zb = ld8h(z2, idx);
#pragma unroll
      for (int i=0;i<4;++i){
        z1c.h[i] = __hmul2(s1h, za.h[i]);
        z2c.h[i] = __hmul2(s2h, zb.h[i]);
      }
    }

    H8 w1o = z1c, w2o = z2c;
    if (h < H_-1){
      const H8 dn = ONES ? dcalc1(Xh, h+1, w, g)
                         : dcalc(z1, z2, Xh, h+1, w, g, s1h, s2h);
#pragma unroll
      for (int i=0;i<4;++i)
        w1o.h[i] = __hfma2(tth, __hsub2(dn.h[i], d00.h[i]), z1c.h[i]);
    }
    if (w < W_-1){
      const H8 de = ONES ? dcalc1(Xh, h, w+1, g)
                         : dcalc(z1, z2, Xh, h, w+1, g, s1h, s2h);
#pragma unroll
      for (int i=0;i<4;++i)
        w2o.h[i] = __hfma2(tth, __hsub2(de.h[i], d00.h[i]), z2c.h[i]);
    }

    st8h(zout, idx, w1o);
    st8h(zout + HWG, idx, w2o);
    // half2 sum-of-squares with 1/16 prescale (rescaled x256 at reduction)
#pragma unroll
    for (int i=0;i<4;++i){
      const __half2 t1 = __hmul2(w1o.h[i], inv16);
      const __half2 t2 = __hmul2(w2o.h[i], inv16);
      acch1 = __hfma2(t1, t1, acch1);
      acch2 = __hfma2(t2, t2, acch2);
    }
  }

  __shared__ float sm1[256], sm2[256];
  __shared__ int elected;
  {
    const float2 f1 = __half22float2(acch1);
    const float2 f2 = __half22float2(acch2);
    sm1[tid] = (f1.x + f1.y) * 256.f;
    sm2[tid] = (f2.x + f2.y) * 256.f;
  }
  __syncthreads();
  for (int s = 128; s > 0; s >>= 1){
    if (tid < s){ sm1[tid] += sm1[tid+s]; sm2[tid] += sm2[tid+s]; }
    __syncthreads();
  }
  if (tid == 0){
    const int base = blockIdx.x ? 2*H_ : 0;   // disjoint slots per chunk
    ss[base + h]       = sm1[0];
    ss[base + H_ + h]  = sm2[0];
    __threadfence();
    const unsigned old = atomicAdd(cnt, 1u);
    elected = (old == NCTA_STEP - 1u);
  }
  __syncthreads();
  if (elected){
    __threadfence();
    float v1 = 0.f, v2 = 0.f;
    for (int hh = tid; hh < H_; hh += 256){
      v1 += sqrtf(ss[hh]       + ss[2*H_ + hh]);
      v2 += sqrtf(ss[H_ + hh]  + ss[3*H_ + hh]);
    }
    sm1[tid] = v1; sm2[tid] = v2;
    __syncthreads();
    for (int s = 128; s > 0; s >>= 1){
      if (tid < s){ sm1[tid] += sm1[tid+s]; sm2[tid] += sm2[tid+s]; }
      __syncthreads();
    }
    if (tid == 0){
      const float n1 = sm1[0], n2 = sm2[0];
      sc_out[0] = (n1 > 1.f) ? (1.f/n1) : 1.f;
      sc_out[1] = (n2 > 1.f) ? (1.f/n2) : 1.f;
      __threadfence();
      *cnt = 0u;                              // reset for next launch/replay
    }
  }
}

// proxg output: U = X + LMBDA * div(s .* z)   (fp32 base, fp32 epilogue)
__global__ __launch_bounds__(256)
void final_div(const uint4* __restrict__ zin, const float4* __restrict__ Xp,
               const float* __restrict__ sc, float4* __restrict__ U)
{
  const int h   = blockIdx.y;
  const int w0  = blockIdx.x << 8;
  const int tid = threadIdx.x;
  const uint4* __restrict__ z1 = zin;
  const uint4* __restrict__ z2 = zin + HWG;
  const float s1 = sc[0], s2 = sc[1];
#pragma unroll 1
  for (int p = 0; p < 8; ++p){
    const int flat = (p << 8) + tid;
    const int w  = w0 + (flat >> 3);
    const int g  = flat & 7;
    const F8 a = h8f(dz1(z1, h, w, g));
    const F8 b = h8f(dz2(z2, h, w, g));
    const int i4 = (h*W_ + w)*C4_ + 2*g;
    const float4 xp = Xp[i4], xq = Xp[i4+1];
    const float xv[8] = {xp.x,xp.y,xp.z,xp.w, xq.x,xq.y,xq.z,xq.w};
    float r[8];
#pragma unroll
    for (int i = 0; i < 8; ++i)
      r[i] = fmaf(LMBDA, fmaf(s1, a.a[i], s2*b.a[i]), xv[i]);
    U[i4]   = make_float4(r[0], r[1], r[2], r[3]);
    U[i4+1] = make_float4(r[4], r[5], r[6], r[7]);
  }
}

// ---------------- fp16 tensor-core GEMM (single-term, hi-only) ---------------
// Both operands hi-rounded fp16 (11-bit mantissa each). Error ~ sqrt(2) x the
// previous A-hi-only 2-term path: predicted rel_err ~3e-4 (gate 1e-3).
__device__ __forceinline__ void mma_f16(float (&c)[4], const uint32_t* a,
                                        const uint32_t* b){
  asm volatile(
    "mma.sync.aligned.m16n8k16.row.col.f32.f16.f16.f32 "
    "{%0,%1,%2,%3}, {%4,%5,%6,%7}, {%8,%9}, {%0,%1,%2,%3};"
    : "+f"(c[0]), "+f"(c[1]), "+f"(c[2]), "+f"(c[3])
    : "r"(a[0]), "r"(a[1]), "r"(a[2]), "r"(a[3]), "r"(b[0]), "r"(b[1]));
}

#define SAH 20                     // A smem stride (b32 units; 16 used + 4 pad)
#define SBH 20                     // B smem stride
#define SMEM_TC ((128*SAH + 64*SBH)*4)   // 15.3 KB

// out[h][m0:m0+128, 0:64] = cU*Uin + cMM*( [do_p1] Uin@N1  +  A2@Bin[h] ) + cP*Pb
// If outh != nullptr, also writes INV_LMBDA*result to the half8 buffer.
__global__ __launch_bounds__(256)
void gemm_tc(float* __restrict__ out, int out_h, __half* __restrict__ outh,
             const float* __restrict__ Uin,
             const float* __restrict__ N1,
             const float* __restrict__ A2,
             const float* __restrict__ Bin, int bin_h,
             const float* __restrict__ Pb,
             int K2, int do_p1, float cU, float cMM, float cP)
{
  extern __shared__ unsigned smemU[];
  unsigned* Ah = smemU;             // [128][SAH]  A hi, packed half2 (k pairs)
  unsigned* Bh = Ah + 128*SAH;      // [64][SBH]   B hi, transposed packed

  const int h   = blockIdx.y;
  const int m0  = blockIdx.x << 7;
  const int tid = threadIdx.x;
  const int lane = tid & 31, wid = tid >> 5;
  const int wm = wid & 3, wn = wid >> 2;      // 4 x 2 warps over (128m, 64n)
  const int gid = lane >> 2, t4 = lane & 3;

  float acc[2][4][4];
#pragma unroll
  for (int i = 0; i < 2; ++i)
#pragma unroll
    for (int j = 0; j < 4; ++j)
#pragma unroll
      for (int q = 0; q < 4; ++q) acc[i][j][q] = 0.f;

  for (int ph = 0; ph < 2; ++ph){
    const float* Ag; int lda; const float* Bg; int Kp;
    if (ph == 0){
      if (!do_p1) continue;
      Ag = Uin + (size_t)h*32768 + (size_t)m0*64; lda = 64; Bg = N1; Kp = 64;
    } else {
      Ag = A2 + (size_t)m0*K2; lda = K2; Bg = Bin + (size_t)h*bin_h; Kp = K2;
    }
    for (int k0 = 0; k0 < Kp; k0 += 32){
      __syncthreads();
      // fill A chunk 128x32: hi only, packed half2 by k-pairs
      {
        const int row0 = tid >> 3;            // 0..31
        const int k4   = (tid & 7) << 2;      // 0,4,..,28
#pragma unroll
        for (int r = 0; r < 4; ++r){
          const int row = row0 + 32*r;
          const float4 v = *(const float4*)(Ag + (size_t)row*lda + k0 + k4);
          Ah[row*SAH + (k4>>1)]     = h2u(__floats2half2_rn(v.x, v.y));
          Ah[row*SAH + (k4>>1) + 1] = h2u(__floats2half2_rn(v.z, v.w));
        }
      }
      // fill B chunk 32x64: transpose to [n][k2], hi only, packed half2
      {
        const int k2 = tid & 15;              // k-pair index 0..15
        const int n4 = (tid >> 4) << 2;       // 0,4,..,60
        const float* B0 = Bg + (size_t)(k0 + 2*k2)*64 + n4;
        const float4 va = *(const float4*)B0;        // k even row
        const float4 vb = *(const float4*)(B0 + 64); // k odd row
        const float av[4] = {va.x, va.y, va.z, va.w};
        const float bv[4] = {vb.x, vb.y, vb.z, vb.w};
#pragma unroll
        for (int j = 0; j < 4; ++j)
          Bh[(n4+j)*SBH + k2] = h2u(__floats2half2_rn(av[j], bv[j]));
      }
      __syncthreads();
#pragma unroll
      for (int kf = 0; kf < 2; ++kf){         // two k16 fragments per chunk
        const int base = kf*8;
        uint32_t ah[2][4];
#pragma unroll
        for (int fm = 0; fm < 2; ++fm){
          const int r0 = wm*32 + fm*16 + gid;
          ah[fm][0] = Ah[r0*SAH + base + t4];
          ah[fm][1] = Ah[(r0+8)*SAH + base + t4];
          ah[fm][2] = Ah[r0*SAH + base + t4 + 4];
          ah[fm][3] = Ah[(r0+8)*SAH + base + t4 + 4];
        }
        uint32_t bhv[4][2];
#pragma unroll
        for (int fn = 0; fn < 4; ++fn){
          const int n = wn*32 + fn*8 + gid;
          bhv[fn][0] = Bh[n*SBH + base + t4];
          bhv[fn][1] = Bh[n*SBH + base + t4 + 4];
        }
#pragma unroll
        for (int fm = 0; fm < 2; ++fm)
#pragma unroll
          for (int fn = 0; fn < 4; ++fn)
            mma_f16(acc[fm][fn], ah[fm], bhv[fn]);
      }
    }
  }

  // epilogue
  float* Oh = out + (size_t)h*out_h;
  __half* Ohh = outh ? (outh + (size_t)h*out_h) : nullptr;
  const float* Uh = Uin + (size_t)h*32768;
  const float* Ph = Pb  + (size_t)h*32768;
#pragma unroll
  for (int fm = 0; fm < 2; ++fm){
#pragma unroll
    for (int fn = 0; fn < 4; ++fn){
      const int r0 = m0 + wm*32 + fm*16 + gid;
      const int c0 = wn*32 + fn*8 + 2*t4;
#pragma unroll
      for (int half = 0; half < 2; ++half){
        const int r = r0 + 8*half;
        float v0 = cMM * acc[fm][fn][2*half];
        float v1 = cMM * acc[fm][fn][2*half + 1];
        if (cU != 0.f){
          const float2 u = *(const float2*)(Uh + (size_t)r*64 + c0);
          v0 += cU*u.x; v1 += cU*u.y;
        }
        if (cP != 0.f){
          const float2 pv = *(const float2*)(Ph + (size_t)r*64 + c0);
          v0 += cP*pv.x; v1 += cP*pv.y;
        }
        *(float2*)(Oh + (size_t)r*64 + c0) = make_float2(v0, v1);
        if (Ohh)
          *reinterpret_cast<__half2*>(Ohh + (size_t)r*64 + c0) =
            __floats2half2_rn(INV_LMBDA*v0, INV_LMBDA*v1);
      }
    }
  }
}

__global__ void transpose_R(float* __restrict__ Rt, const float* __restrict__ R)
{
  const int i = blockIdx.x*256 + threadIdx.x;
  if (i < W_*WM_){
    const int w = i / WM_, m = i % WM_;
    Rt[i] = R[m*W_ + w];
  }
}

__global__ void compute_M1(float* __restrict__ M1, const float* __restrict__ B,
                           const float* __restrict__ Bt)
{
  const int i = blockIdx.x*256 + threadIdx.x;
  if (i < C_*C_){
    const int m = i >> 6, n = i & 63;
    float s = 0.f;
#pragma unroll 8
    for (int k = 0; k < C_; ++k) s += B[m*C_ + k]*Bt[k*C_ + n];
    M1[i] = s;
  }
}

// ---------------- driver ----------------------------------------------------
extern "C" void kernel_launch(void* const* d_in, const int* in_sizes, int n_in,
                              void* d_out, int out_size)
{
  const float* Y_H = (const float*)d_in[0];
  const float* Y_M = (const float*)d_in[1];
  const float* B   = (const float*)d_in[2];
  const float* B_t = (const float*)d_in[3];
  const float* R   = (const float*)d_in[4];
  float* U = (float*)d_out;

  uint4 *zA, *zB, *Xh, *Ph;
  float4 *X, *P;
  float *T, *M1, *Rt, *ss, *sc;
  unsigned* cnt;
  cudaGetSymbolAddress((void**)&zA,  g_zA);
  cudaGetSymbolAddress((void**)&zB,  g_zB);
  cudaGetSymbolAddress((void**)&X,   g_X);
  cudaGetSymbolAddress((void**)&P,   g_P);
  cudaGetSymbolAddress((void**)&Xh,  g_Xh);
  cudaGetSymbolAddress((void**)&Ph,  g_Ph);
  cudaGetSymbolAddress((void**)&T,   g_T);
  cudaGetSymbolAddress((void**)&M1,  g_M1);
  cudaGetSymbolAddress((void**)&Rt,  g_Rt);
  cudaGetSymbolAddress((void**)&ss,  g_ss);
  cudaGetSymbolAddress((void**)&sc,  g_sc);
  cudaGetSymbolAddress((void**)&cnt, g_cnt);

  const dim3 blk2(256);
  const dim3 grd2(2, H_);

  transpose_R<<<(W_*WM_ + 255)/256, 256>>>(Rt, R);
  compute_M1 <<<(C_*C_ + 255)/256, 256>>>(M1, B, B_t);
  // P = LMBDA*(Y_H@B_t + Rt@Y_M), plus Ph = 10*P in half
  gemm_tc<<<dim3(4, H_), 256, SMEM_TC>>>((float*)P, 32768, (__half*)Ph,
                                         Y_H, B_t, Rt, Y_M, WM_*C_,
                                         (const float*)P,
                                         WM_, 1, 0.f, LMBDA, 0.f);

  uint4* zbuf[2] = { zA, zB };
  for (int it = 0; it < 5; ++it){
    const uint4* Xhp;
    const float4* Xp;
    if (it == 0){
      Xhp = Ph; Xp = P;                         // U = 0 -> X = P exactly
    } else {
      // T[h] = R @ U[h]
      gemm_tc<<<dim3(1, H_), 256, SMEM_TC>>>(T, WM_*C_, (__half*)nullptr,
                                             U, M1, R, U, W_*C_,
                                             (const float*)P,
                                             W_, 0, 0.f, 1.f, 0.f);
      // X = U - LMBDA*(U@M1 + Rt@T) + P, plus Xh = 10*X in half
      gemm_tc<<<dim3(4, H_), 256, SMEM_TC>>>((float*)X, 32768, (__half*)Xh,
                                             U, M1, Rt, T, WM_*C_,
                                             (const float*)P,
                                             WM_, 1, 1.f, -LMBDA, 1.f);
      Xhp = Xh; Xp = X;
    }
    inner_step<true><<<grd2, blk2>>>(zbuf[1], zbuf[0], Xhp, sc, ss, sc, cnt);
    for (int j = 1; j < 5; ++j){
      inner_step<false><<<grd2, blk2>>>(zbuf[(j-1)&1], zbuf[j&1], Xhp,
                                        sc, ss, sc, cnt);
    }
    final_div<<<grd2, blk2>>>(zbuf[0], Xp, sc, (float4*)U);
  }
}

// round 14
// speedup vs baseline: 1.2162x; 1.0294x over previous
#include <cuda_runtime.h>
#include <cuda_fp16.h>
#include <cstdint>

#define H_ 512
#define W_ 512
#define C_ 64
#define WM_ 128
#define G8_ 8                       // half8 groups per pixel (C=64 -> 8 groups)
#define C4_ 16                      // float4 per pixel
#define HWG (H_*W_*G8_)             // uint4 elements per z component plane
#define HWC4 (H_*W_*C4_)
#define LMBDA 0.1f
#define INV_LMBDA 10.0f
#define TAU 0.1f
#define NCTA_STEP 1024u             // persistent grid = (2, H) = 1024 CTAs

// ---------------- scratch (static device globals; no allocations) ----------
static __device__ uint4  g_zA[2*HWG];       // z ping (half): [comp][h][w][g]
static __device__ uint4  g_zB[2*HWG];       // z pong
static __device__ float4 g_X [HWC4];        // X = U - lambda*grad_f(U)   (fp32)
static __device__ float4 g_P [HWC4];        // P = lambda*(Y_H@B_t + R^T@Y_M)
static __device__ uint4  g_Xh[HWG];         // 10*X in half8 (stencil operand)
static __device__ uint4  g_Ph[HWG];         // 10*P in half8
static __device__ float  g_T [H_*WM_*C_];   // T[h] = R @ U[h]
static __device__ float  g_M1[C_*C_];       // M1 = B @ B_t
static __device__ float  g_Rt[W_*WM_];      // R^T
static __device__ float  g_ss[4*H_];        // wide partials [chunk][comp][h]
static __device__ float  g_sc[2];           // projection scales (s1, s2)
static __device__ unsigned g_cnt;           // step arrival counter (self-reset)
static __device__ unsigned g_gen;           // barrier generation flag
static __device__ unsigned g_cnt2;          // exit counter (self-reset)

// ---------------- half8 (H8) utilities --------------------------------------
struct H8 { __half2 h[4]; };

__device__ __forceinline__ __half2 u2h(unsigned u){
  __half2 r; *reinterpret_cast<unsigned*>(&r) = u; return r;
}
__device__ __forceinline__ unsigned h2u(__half2 h){
  return *reinterpret_cast<unsigned*>(&h);
}
__device__ __forceinline__ H8 ld8h(const uint4* __restrict__ p, int idx){
  const uint4 v = p[idx];
  H8 r; r.h[0]=u2h(v.x); r.h[1]=u2h(v.y); r.h[2]=u2h(v.z); r.h[3]=u2h(v.w);
  return r;
}
__device__ __forceinline__ void st8h(uint4* __restrict__ p, int idx, const H8& r){
  p[idx] = make_uint4(h2u(r.h[0]), h2u(r.h[1]), h2u(r.h[2]), h2u(r.h[3]));
}
__device__ __forceinline__ H8 h8sub(H8 a, H8 b){ H8 r;
#pragma unroll
  for (int i=0;i<4;++i) r.h[i]=__hsub2(a.h[i],b.h[i]); return r; }
__device__ __forceinline__ H8 h8neg(H8 a){ H8 r;
#pragma unroll
  for (int i=0;i<4;++i) r.h[i]=__hneg2(a.h[i]); return r; }

// dz components (Chambolle adjoint), half arithmetic
__device__ __forceinline__ H8 dz1(const uint4* __restrict__ z1, int h, int w, int g){
  if (h == 0)     return ld8h(z1, w*G8_ + g);
  if (h == H_-1)  return h8neg(ld8h(z1, ((H_-2)*W_ + w)*G8_ + g));
  return h8sub(ld8h(z1, (h*W_ + w)*G8_ + g), ld8h(z1, ((h-1)*W_ + w)*G8_ + g));
}
__device__ __forceinline__ H8 dz2(const uint4* __restrict__ z2, int h, int w, int g){
  if (w == 0)     return ld8h(z2, (h*W_)*G8_ + g);
  if (w == W_-1)  return h8neg(ld8h(z2, (h*W_ + (W_-2))*G8_ + g));
  return h8sub(ld8h(z2, (h*W_ + w)*G8_ + g), ld8h(z2, (h*W_ + (w-1))*G8_ + g));
}

// d = s1*dz1 + s2*dz2 + Xh (Xh pre-scaled by 1/lambda)
__device__ __forceinline__ H8 dcalc(const uint4* __restrict__ z1,
                                    const uint4* __restrict__ z2,
                                    const uint4* __restrict__ Xh,
                                    int h, int w, int g, __half2 s1h, __half2 s2h){
  const H8 a = dz1(z1, h, w, g);
  const H8 b = dz2(z2, h, w, g);
  const H8 x = ld8h(Xh, (h*W_ + w)*G8_ + g);
  H8 d;
#pragma unroll
  for (int i=0;i<4;++i)
    d.h[i] = __hfma2(s1h, a.h[i], __hfma2(s2h, b.h[i], x.h[i]));
  return d;
}
// ONES variant: z == 1 -> dz terms are edge constants
__device__ __forceinline__ H8 dcalc1(const uint4* __restrict__ Xh, int h, int w, int g){
  const float a = (h==0)?1.f:((h==H_-1)?-1.f:0.f);
  const float b = (w==0)?1.f:((w==W_-1)?-1.f:0.f);
  const __half2 e = __float2half2_rn(a + b);
  const H8 x = ld8h(Xh, (h*W_ + w)*G8_ + g);
  H8 d;
#pragma unroll
  for (int i=0;i<4;++i) d.h[i] = __hadd2(x.h[i], e);
  return d;
}

// ---------------- fp32 helpers for final_div --------------------------------
struct F8 { float a[8]; };
__device__ __forceinline__ F8 h8f(const H8& x){
  F8 r;
#pragma unroll
  for (int i=0;i<4;++i){
    const float2 f = __half22float2(x.h[i]);
    r.a[2*i] = f.x; r.a[2*i+1] = f.y;
  }
  return r;
}

// ---------------- one dual-iteration step body -------------------------------
template<bool ONES>
__device__ __forceinline__ void step_body(const uint4* __restrict__ zin,
                                          uint4* __restrict__ zout,
                                          const uint4* __restrict__ Xh,
                                          __half2 s1h, __half2 s2h,
                                          int h, int w0, int tid,
                                          float& out1, float& out2)
{
  const uint4* __restrict__ z1 = zin;
  const uint4* __restrict__ z2 = zin + HWG;
  const __half2 tth = __float2half2_rn(2.f * TAU);
  const __half2 one = __float2half2_rn(1.f);
  const __half2 inv16 = __float2half2_rn(0.0625f);
  __half2 acch1 = __float2half2_rn(0.f);
  __half2 acch2 = __float2half2_rn(0.f);

#pragma unroll 1
  for (int p = 0; p < 8; ++p){
    const int flat = (p << 8) + tid;       // 0..2047
    const int w  = w0 + (flat >> 3);
    const int g  = flat & 7;
    const int idx = (h*W_ + w)*G8_ + g;

    H8 d00, z1c, z2c;
    if (ONES){
      d00 = dcalc1(Xh, h, w, g);
#pragma unroll
      for (int i=0;i<4;++i){ z1c.h[i] = one; z2c.h[i] = one; }
    } else {
      d00 = dcalc(z1, z2, Xh, h, w, g, s1h, s2h);
      const H8 za = ld8h(z1, idx), zb = ld8h(z2, idx);
#pragma unroll
      for (int i=0;i<4;++i){
        z1c.h[i] = __hmul2(s1h, za.h[i]);
        z2c.h[i] = __hmul2(s2h, zb.h[i]);
      }
    }

    H8 w1o = z1c, w2o = z2c;
    if (h < H_-1){
      const H8 dn = ONES ? dcalc1(Xh, h+1, w, g)
                         : dcalc(z1, z2, Xh, h+1, w, g, s1h, s2h);
#pragma unroll
      for (int i=0;i<4;++i)
        w1o.h[i] = __hfma2(tth, __hsub2(dn.h[i], d00.h[i]), z1c.h[i]);
    }
    if (w < W_-1){
      const H8 de = ONES ? dcalc1(Xh, h, w+1, g)
                         : dcalc(z1, z2, Xh, h, w+1, g, s1h, s2h);
#pragma unroll
      for (int i=0;i<4;++i)
        w2o.h[i] = __hfma2(tth, __hsub2(de.h[i], d00.h[i]), z2c.h[i]);
    }

    st8h(zout, idx, w1o);
    st8h(zout + HWG, idx, w2o);
#pragma unroll
    for (int i=0;i<4;++i){
      const __half2 t1 = __hmul2(w1o.h[i], inv16);
      const __half2 t2 = __hmul2(w2o.h[i], inv16);
      acch1 = __hfma2(t1, t1, acch1);
      acch2 = __hfma2(t2, t2, acch2);
    }
  }
  const float2 f1 = __half22float2(acch1);
  const float2 f2 = __half22float2(acch2);
  out1 = (f1.x + f1.y) * 256.f;
  out2 = (f2.x + f2.y) * 256.f;
}

// ---------------- grid barrier + projection-scale publication ----------------
// Each CTA reduces its partial, writes its ss slot, arrives; the LAST CTA
// reduces ss -> scales (fixed order, deterministic), resets the arrival
// counter, and bumps the generation flag everyone spins on.
__device__ __forceinline__ void reduce_and_sync(
    unsigned target, int h, int chunkbase, float v1, float v2,
    float* __restrict__ ss, float* __restrict__ sc,
    unsigned* __restrict__ cnt, volatile unsigned* gen,
    float* sm1, float* sm2, int* elected, int tid)
{
  sm1[tid] = v1; sm2[tid] = v2;
  __syncthreads();
  for (int s = 128; s > 0; s >>= 1){
    if (tid < s){ sm1[tid] += sm1[tid+s]; sm2[tid] += sm2[tid+s]; }
    __syncthreads();
  }
  if (tid == 0){
    ss[chunkbase + h]      = sm1[0];
    ss[chunkbase + H_ + h] = sm2[0];
    __threadfence();
    *elected = (atomicAdd(cnt, 1u) == NCTA_STEP - 1u);
  }
  __syncthreads();
  if (*elected){
    __threadfence();
    float w1 = 0.f, w2 = 0.f;
    for (int hh = tid; hh < H_; hh += 256){
      w1 += sqrtf(ss[hh]       + ss[2*H_ + hh]);
      w2 += sqrtf(ss[H_ + hh]  + ss[3*H_ + hh]);
    }
    sm1[tid] = w1; sm2[tid] = w2;
    __syncthreads();
    for (int s = 128; s > 0; s >>= 1){
      if (tid < s){ sm1[tid] += sm1[tid+s]; sm2[tid] += sm2[tid+s]; }
      __syncthreads();
    }
    if (tid == 0){
      const float n1 = sm1[0], n2 = sm2[0];
      sc[0] = (n1 > 1.f) ? (1.f/n1) : 1.f;
      sc[1] = (n2 > 1.f) ? (1.f/n2) : 1.f;
      __threadfence();
      *cnt = 0u;                 // re-arm arrivals for the next step
      *gen = target;             // release
    }
  }
  if (tid == 0){
    while (*gen < target) __nanosleep(64);
  }
  __syncthreads();
  __threadfence();               // acquire side: order subsequent z reads
}

// ---------------- persistent inner loop: 5 dual iterations, 1 launch ---------
// grid (2, H) = 1024 CTAs; all co-resident (8 CTAs/SM by threads, 148 SMs).
__global__ __launch_bounds__(256, 8)
void inner_persist(uint4* __restrict__ z_a, uint4* __restrict__ z_b,
                   const uint4* __restrict__ Xh,
                   float* __restrict__ ss, float* __restrict__ sc,
                   unsigned* __restrict__ cnt, unsigned* __restrict__ gen,
                   unsigned* __restrict__ cnt2)
{
  const int h   = blockIdx.y;
  const int w0  = blockIdx.x << 8;
  const int tid = threadIdx.x;
  const int chunkbase = blockIdx.x ? 2*H_ : 0;
  __shared__ float sm1[256], sm2[256];
  __shared__ int elected;
  volatile unsigned* vgen = (volatile unsigned*)gen;

  float a1, a2;
  // step 0: z == ones
  {
    const __half2 one = __float2half2_rn(1.f);
    step_body<true>(z_b, z_a, Xh, one, one, h, w0, tid, a1, a2);
    reduce_and_sync(1u, h, chunkbase, a1, a2, ss, sc, cnt, vgen,
                    sm1, sm2, &elected, tid);
  }
  // steps 1..4
#pragma unroll 1
  for (int j = 1; j < 5; ++j){
    const float s1 = sc[0], s2 = sc[1];
    const __half2 s1h = __float2half2_rn(s1);
    const __half2 s2h = __float2half2_rn(s2);
    const uint4* zi = (j & 1) ? z_a : z_b;
    uint4*       zo = (j & 1) ? z_b : z_a;
    step_body<false>(zi, zo, Xh, s1h, s2h, h, w0, tid, a1, a2);
    reduce_and_sync((unsigned)(j + 1), h, chunkbase, a1, a2, ss, sc, cnt, vgen,
                    sm1, sm2, &elected, tid);
  }
  // exit: last CTA resets the generation flag for the next launch / replay
  if (tid == 0){
    const unsigned old = atomicAdd(cnt2, 1u);
    if (old == NCTA_STEP - 1u){
      *vgen = 0u;
      *cnt2 = 0u;
    }
  }
}

// proxg output: U = X + LMBDA * div(s .* z)   (fp32 base, fp32 epilogue)
__global__ __launch_bounds__(256)
void final_div(const uint4* __restrict__ zin, const float4* __restrict__ Xp,
               const float* __restrict__ sc, float4* __restrict__ U)
{
  const int h   = blockIdx.y;
  const int w0  = blockIdx.x << 8;
  const int tid = threadIdx.x;
  const uint4* __restrict__ z1 = zin;
  const uint4* __restrict__ z2 = zin + HWG;
  const float s1 = sc[0], s2 = sc[1];
#pragma unroll 1
  for (int p = 0; p < 8; ++p){
    const int flat = (p << 8) + tid;
    const int w  = w0 + (flat >> 3);
    const int g  = flat & 7;
    const F8 a = h8f(dz1(z1, h, w, g));
    const F8 b = h8f(dz2(z2, h, w, g));
    const int i4 = (h*W_ + w)*C4_ + 2*g;
    const float4 xp = Xp[i4], xq = Xp[i4+1];
    const float xv[8] = {xp.x,xp.y,xp.z,xp.w, xq.x,xq.y,xq.z,xq.w};
    float r[8];
#pragma unroll
    for (int i = 0; i < 8; ++i)
      r[i] = fmaf(LMBDA, fmaf(s1, a.a[i], s2*b.a[i]), xv[i]);
    U[i4]   = make_float4(r[0], r[1], r[2], r[3]);
    U[i4+1] = make_float4(r[4], r[5], r[6], r[7]);
  }
}

// ---------------- fp16 tensor-core GEMM (single-term, hi-only) ---------------
__device__ __forceinline__ void mma_f16(float (&c)[4], const uint32_t* a,
                                        const uint32_t* b){
  asm volatile(
    "mma.sync.aligned.m16n8k16.row.col.f32.f16.f16.f32 "
    "{%0,%1,%2,%3}, {%4,%5,%6,%7}, {%8,%9}, {%0,%1,%2,%3};"
    : "+f"(c[0]), "+f"(c[1]), "+f"(c[2]), "+f"(c[3])
    : "r"(a[0]), "r"(a[1]), "r"(a[2]), "r"(a[3]), "r"(b[0]), "r"(b[1]));
}

#define SAH 20                     // A smem stride (b32 units; 16 used + 4 pad)
#define SBH 20                     // B smem stride
#define SMEM_TC ((128*SAH + 64*SBH)*4)   // 15.3 KB

// out[h][m0:m0+128, 0:64] = cU*Uin + cMM*( [do_p1] Uin@N1  +  A2@Bin[h] ) + cP*Pb
// If outh != nullptr, also writes INV_LMBDA*result to the half8 buffer.
__global__ __launch_bounds__(256)
void gemm_tc(float* __restrict__ out, int out_h, __half* __restrict__ outh,
             const float* __restrict__ Uin,
             const float* __restrict__ N1,
             const float* __restrict__ A2,
             const float* __restrict__ Bin, int bin_h,
             const float* __restrict__ Pb,
             int K2, int do_p1, float cU, float cMM, float cP)
{
  extern __shared__ unsigned smemU[];
  unsigned* Ah = smemU;             // [128][SAH]  A hi, packed half2 (k pairs)
  unsigned* Bh = Ah + 128*SAH;      // [64][SBH]   B hi, transposed packed

  const int h   = blockIdx.y;
  const int m0  = blockIdx.x << 7;
  const int tid = threadIdx.x;
  const int lane = tid & 31, wid = tid >> 5;
  const int wm = wid & 3, wn = wid >> 2;      // 4 x 2 warps over (128m, 64n)
  const int gid = lane >> 2, t4 = lane & 3;

  float acc[2][4][4];
#pragma unroll
  for (int i = 0; i < 2; ++i)
#pragma unroll
    for (int j = 0; j < 4; ++j)
#pragma unroll
      for (int q = 0; q < 4; ++q) acc[i][j][q] = 0.f;

  for (int ph = 0; ph < 2; ++ph){
    const float* Ag; int lda; const float* Bg; int Kp;
    if (ph == 0){
      if (!do_p1) continue;
      Ag = Uin + (size_t)h*32768 + (size_t)m0*64; lda = 64; Bg = N1; Kp = 64;
    } else {
      Ag = A2 + (size_t)m0*K2; lda = K2; Bg = Bin + (size_t)h*bin_h; Kp = K2;
    }
    for (int k0 = 0; k0 < Kp; k0 += 32){
      __syncthreads();
      // fill A chunk 128x32: hi only, packed half2 by k-pairs
      {
        const int row0 = tid >> 3;            // 0..31
        const int k4   = (tid & 7) << 2;      // 0,4,..,28
#pragma unroll
        for (int r = 0; r < 4; ++r){
          const int row = row0 + 32*r;
          const float4 v = *(const float4*)(Ag + (size_t)row*lda + k0 + k4);
          Ah[row*SAH + (k4>>1)]     = h2u(__floats2half2_rn(v.x, v.y));
          Ah[row*SAH + (k4>>1) + 1] = h2u(__floats2half2_rn(v.z, v.w));
        }
      }
      // fill B chunk 32x64: transpose to [n][k2], hi only, packed half2
      {
        const int k2 = tid & 15;              // k-pair index 0..15
        const int n4 = (tid >> 4) << 2;       // 0,4,..,60
        const float* B0 = Bg + (size_t)(k0 + 2*k2)*64 + n4;
        const float4 va = *(const float4*)B0;        // k even row
        const float4 vb = *(const float4*)(B0 + 64); // k odd row
        const float av[4] = {va.x, va.y, va.z, va.w};
        const float bv[4] = {vb.x, vb.y, vb.z, vb.w};
#pragma unroll
        for (int j = 0; j < 4; ++j)
          Bh[(n4+j)*SBH + k2] = h2u(__floats2half2_rn(av[j], bv[j]));
      }
      __syncthreads();
#pragma unroll
      for (int kf = 0; kf < 2; ++kf){         // two k16 fragments per chunk
        const int base = kf*8;
        uint32_t ah[2][4];
#pragma unroll
        for (int fm = 0; fm < 2; ++fm){
          const int r0 = wm*32 + fm*16 + gid;
          ah[fm][0] = Ah[r0*SAH + base + t4];
          ah[fm][1] = Ah[(r0+8)*SAH + base + t4];
          ah[fm][2] = Ah[r0*SAH + base + t4 + 4];
          ah[fm][3] = Ah[(r0+8)*SAH + base + t4 + 4];
        }
        uint32_t bhv[4][2];
#pragma unroll
        for (int fn = 0; fn < 4; ++fn){
          const int n = wn*32 + fn*8 + gid;
          bhv[fn][0] = Bh[n*SBH + base + t4];
          bhv[fn][1] = Bh[n*SBH + base + t4 + 4];
        }
#pragma unroll
        for (int fm = 0; fm < 2; ++fm)
#pragma unroll
          for (int fn = 0; fn < 4; ++fn)
            mma_f16(acc[fm][fn], ah[fm], bhv[fn]);
      }
    }
  }

  // epilogue
  float* Oh = out + (size_t)h*out_h;
  __half* Ohh = outh ? (outh + (size_t)h*out_h) : nullptr;
  const float* Uh = Uin + (size_t)h*32768;
  const float* Ph = Pb  + (size_t)h*32768;
#pragma unroll
  for (int fm = 0; fm < 2; ++fm){
#pragma unroll
    for (int fn = 0; fn < 4; ++fn){
      const int r0 = m0 + wm*32 + fm*16 + gid;
      const int c0 = wn*32 + fn*8 + 2*t4;
#pragma unroll
      for (int half = 0; half < 2; ++half){
        const int r = r0 + 8*half;
        float v0 = cMM * acc[fm][fn][2*half];
        float v1 = cMM * acc[fm][fn][2*half + 1];
        if (cU != 0.f){
          const float2 u = *(const float2*)(Uh + (size_t)r*64 + c0);
          v0 += cU*u.x; v1 += cU*u.y;
        }
        if (cP != 0.f){
          const float2 pv = *(const float2*)(Ph + (size_t)r*64 + c0);
          v0 += cP*pv.x; v1 += cP*pv.y;
        }
        *(float2*)(Oh + (size_t)r*64 + c0) = make_float2(v0, v1);
        if (Ohh)
          *reinterpret_cast<__half2*>(Ohh + (size_t)r*64 + c0) =
            __floats2half2_rn(INV_LMBDA*v0, INV_LMBDA*v1);
      }
    }
  }
}

__global__ void transpose_R(float* __restrict__ Rt, const float* __restrict__ R)
{
  const int i = blockIdx.x*256 + threadIdx.x;
  if (i < W_*WM_){
    const int w = i / WM_, m = i % WM_;
    Rt[i] = R[m*W_ + w];
  }
}

__global__ void compute_M1(float* __restrict__ M1, const float* __restrict__ B,
                           const float* __restrict__ Bt)
{
  const int i = blockIdx.x*256 + threadIdx.x;
  if (i < C_*C_){
    const int m = i >> 6, n = i & 63;
    float s = 0.f;
#pragma unroll 8
    for (int k = 0; k < C_; ++k) s += B[m*C_ + k]*Bt[k*C_ + n];
    M1[i] = s;
  }
}

// ---------------- driver ----------------------------------------------------
extern "C" void kernel_launch(void* const* d_in, const int* in_sizes, int n_in,
                              void* d_out, int out_size)
{
  const float* Y_H = (const float*)d_in[0];
  const float* Y_M = (const float*)d_in[1];
  const float* B   = (const float*)d_in[2];
  const float* B_t = (const float*)d_in[3];
  const float* R   = (const float*)d_in[4];
  float* U = (float*)d_out;

  uint4 *zA, *zB, *Xh, *Ph;
  float4 *X, *P;
  float *T, *M1, *Rt, *ss, *sc;
  unsigned *cnt, *gen, *cnt2;
  cudaGetSymbolAddress((void**)&zA,   g_zA);
  cudaGetSymbolAddress((void**)&zB,   g_zB);
  cudaGetSymbolAddress((void**)&X,    g_X);
  cudaGetSymbolAddress((void**)&P,    g_P);
  cudaGetSymbolAddress((void**)&Xh,   g_Xh);
  cudaGetSymbolAddress((void**)&Ph,   g_Ph);
  cudaGetSymbolAddress((void**)&T,    g_T);
  cudaGetSymbolAddress((void**)&M1,   g_M1);
  cudaGetSymbolAddress((void**)&Rt,   g_Rt);
  cudaGetSymbolAddress((void**)&ss,   g_ss);
  cudaGetSymbolAddress((void**)&sc,   g_sc);
  cudaGetSymbolAddress((void**)&cnt,  g_cnt);
  cudaGetSymbolAddress((void**)&gen,  g_gen);
  cudaGetSymbolAddress((void**)&cnt2, g_cnt2);

  const dim3 blk2(256);
  const dim3 grd2(2, H_);

  transpose_R<<<(W_*WM_ + 255)/256, 256>>>(Rt, R);
  compute_M1 <<<(C_*C_ + 255)/256, 256>>>(M1, B, B_t);
  // P = LMBDA*(Y_H@B_t + Rt@Y_M), plus Ph = 10*P in half
  gemm_tc<<<dim3(4, H_), 256, SMEM_TC>>>((float*)P, 32768, (__half*)Ph,
                                         Y_H, B_t, Rt, Y_M, WM_*C_,
                                         (const float*)P,
                                         WM_, 1, 0.f, LMBDA, 0.f);

  for (int it = 0; it < 5; ++it){
    const uint4* Xhp;
    const float4* Xp;
    if (it == 0){
      Xhp = Ph; Xp = P;                         // U = 0 -> X = P exactly
    } else {
      // T[h] = R @ U[h]
      gemm_tc<<<dim3(1, H_), 256, SMEM_TC>>>(T, WM_*C_, (__half*)nullptr,
                                             U, M1, R, U, W_*C_,
                                             (const float*)P,
                                             W_, 0, 0.f, 1.f, 0.f);
      // X = U - LMBDA*(U@M1 + Rt@T) + P, plus Xh = 10*X in half
      gemm_tc<<<dim3(4, H_), 256, SMEM_TC>>>((float*)X, 32768, (__half*)Xh,
                                             U, M1, Rt, T, WM_*C_,
                                             (const float*)P,
                                             WM_, 1, 1.f, -LMBDA, 1.f);
      Xhp = Xh; Xp = X;
    }
    // all 5 dual iterations in ONE persistent launch (grid-barrier between)
    inner_persist<<<grd2, blk2>>>(zA, zB, (const uint4*)Xhp, ss, sc,
                                  cnt, gen, cnt2);
    // last step wrote zA; scales in sc
    final_div<<<grd2, blk2>>>(zA, Xp, sc, (float4*)U);
  }
}

// round 17
// speedup vs baseline: 1.2330x; 1.0139x over previous
#include <cuda_runtime.h>
#include <cuda_fp16.h>
#include <cstdint>

#define H_ 512
#define W_ 512
#define C_ 64
#define WM_ 128
#define G8_ 8                       // half8 groups per pixel (C=64 -> 8 groups)
#define C4_ 16                      // float4 per pixel
#define HWG (H_*W_*G8_)             // uint4 elements per z component plane
#define HWC4 (H_*W_*C4_)
#define LMBDA 0.1f
#define INV_LMBDA 10.0f
#define TAU 0.1f
#define NCTA_STEP 1024u             // persistent grid = (2, H) = 1024 CTAs

// ---------------- scratch (static device globals; no allocations) ----------
static __device__ uint4  g_zA[2*HWG];       // z ping (half): [comp][h][w][g]
static __device__ uint4  g_zB[2*HWG];       // z pong
static __device__ float4 g_X [HWC4];        // X = U - lambda*grad_f(U)   (fp32)
static __device__ float4 g_P [HWC4];        // P = lambda*(Y_H@B_t + R^T@Y_M)
static __device__ uint4  g_Xh[HWG];         // 10*X in half8 (stencil operand)
static __device__ uint4  g_Ph[HWG];         // 10*P in half8
static __device__ float  g_T [H_*WM_*C_];   // T[h] = R @ U[h]
static __device__ float  g_M1[C_*C_];       // M1 = B @ B_t
static __device__ float  g_Rt[W_*WM_];      // R^T
static __device__ float  g_ss[4*H_];        // wide partials [chunk][comp][h]
static __device__ float  g_sc[2];           // projection scales (s1, s2)
static __device__ unsigned g_cnt;           // step arrival counter (self-reset)
static __device__ unsigned g_gen;           // barrier generation flag
static __device__ unsigned g_cnt2;          // exit counter (self-reset)

// ---------------- half8 (H8) utilities --------------------------------------
struct H8 { __half2 h[4]; };

__device__ __forceinline__ __half2 u2h(unsigned u){
  __half2 r; *reinterpret_cast<unsigned*>(&r) = u; return r;
}
__device__ __forceinline__ unsigned h2u(__half2 h){
  return *reinterpret_cast<unsigned*>(&h);
}
__device__ __forceinline__ H8 ld8h(const uint4* __restrict__ p, int idx){
  const uint4 v = p[idx];
  H8 r; r.h[0]=u2h(v.x); r.h[1]=u2h(v.y); r.h[2]=u2h(v.z); r.h[3]=u2h(v.w);
  return r;
}
__device__ __forceinline__ void st8h(uint4* __restrict__ p, int idx, const H8& r){
  p[idx] = make_uint4(h2u(r.h[0]), h2u(r.h[1]), h2u(r.h[2]), h2u(r.h[3]));
}
__device__ __forceinline__ H8 h8sub(H8 a, H8 b){ H8 r;
#pragma unroll
  for (int i=0;i<4;++i) r.h[i]=__hsub2(a.h[i],b.h[i]); return r; }
__device__ __forceinline__ H8 h8neg(H8 a){ H8 r;
#pragma unroll
  for (int i=0;i<4;++i) r.h[i]=__hneg2(a.h[i]); return r; }

// dz components (Chambolle adjoint), half arithmetic
__device__ __forceinline__ H8 dz1(const uint4* __restrict__ z1, int h, int w, int g){
  if (h == 0)     return ld8h(z1, w*G8_ + g);
  if (h == H_-1)  return h8neg(ld8h(z1, ((H_-2)*W_ + w)*G8_ + g));
  return h8sub(ld8h(z1, (h*W_ + w)*G8_ + g), ld8h(z1, ((h-1)*W_ + w)*G8_ + g));
}
__device__ __forceinline__ H8 dz2(const uint4* __restrict__ z2, int h, int w, int g){
  if (w == 0)     return ld8h(z2, (h*W_)*G8_ + g);
  if (w == W_-1)  return h8neg(ld8h(z2, (h*W_ + (W_-2))*G8_ + g));
  return h8sub(ld8h(z2, (h*W_ + w)*G8_ + g), ld8h(z2, (h*W_ + (w-1))*G8_ + g));
}

// d = s1*dz1 + s2*dz2 + Xh (Xh pre-scaled by 1/lambda)
__device__ __forceinline__ H8 dcalc(const uint4* __restrict__ z1,
                                    const uint4* __restrict__ z2,
                                    const uint4* __restrict__ Xh,
                                    int h, int w, int g, __half2 s1h, __half2 s2h){
  const H8 a = dz1(z1, h, w, g);
  const H8 b = dz2(z2, h, w, g);
  const H8 x = ld8h(Xh, (h*W_ + w)*G8_ + g);
  H8 d;
#pragma unroll
  for (int i=0;i<4;++i)
    d.h[i] = __hfma2(s1h, a.h[i], __hfma2(s2h, b.h[i], x.h[i]));
  return d;
}
// ONES variant: z == 1 -> dz terms are edge constants
__device__ __forceinline__ H8 dcalc1(const uint4* __restrict__ Xh, int h, int w, int g){
  const float a = (h==0)?1.f:((h==H_-1)?-1.f:0.f);
  const float b = (w==0)?1.f:((w==W_-1)?-1.f:0.f);
  const __half2 e = __float2half2_rn(a + b);
  const H8 x = ld8h(Xh, (h*W_ + w)*G8_ + g);
  H8 d;
#pragma unroll
  for (int i=0;i<4;++i) d.h[i] = __hadd2(x.h[i], e);
  return d;
}

// ---------------- fp32 helpers for the final-div phase -----------------------
struct F8 { float a[8]; };
__device__ __forceinline__ F8 h8f(const H8& x){
  F8 r;
#pragma unroll
  for (int i=0;i<4;++i){
    const float2 f = __half22float2(x.h[i]);
    r.a[2*i] = f.x; r.a[2*i+1] = f.y;
  }
  return r;
}

// ---------------- one dual-iteration step body -------------------------------
template<bool ONES>
__device__ __forceinline__ void step_body(const uint4* __restrict__ zin,
                                          uint4* __restrict__ zout,
                                          const uint4* __restrict__ Xh,
                                          __half2 s1h, __half2 s2h,
                                          int h, int w0, int tid,
                                          float& out1, float& out2)
{
  const uint4* __restrict__ z1 = zin;
  const uint4* __restrict__ z2 = zin + HWG;
  const __half2 tth = __float2half2_rn(2.f * TAU);
  const __half2 one = __float2half2_rn(1.f);
  const __half2 inv16 = __float2half2_rn(0.0625f);
  __half2 acch1 = __float2half2_rn(0.f);
  __half2 acch2 = __float2half2_rn(0.f);

#pragma unroll 1
  for (int p = 0; p < 8; ++p){
    const int flat = (p << 8) + tid;       // 0..2047
    const int w  = w0 + (flat >> 3);
    const int g  = flat & 7;
    const int idx = (h*W_ + w)*G8_ + g;

    H8 d00, z1c, z2c;
    if (ONES){
      d00 = dcalc1(Xh, h, w, g);
#pragma unroll
      for (int i=0;i<4;++i){ z1c.h[i] = one; z2c.h[i] = one; }
    } else {
      d00 = dcalc(z1, z2, Xh, h, w, g, s1h, s2h);
      const H8 za = ld8h(z1, idx), zb = ld8h(z2, idx);
#pragma unroll
      for (int i=0;i<4;++i){
        z1c.h[i] = __hmul2(s1h, za.h[i]);
        z2c.h[i] = __hmul2(s2h, zb.h[i]);
      }
    }

    H8 w1o = z1c, w2o = z2c;
    if (h < H_-1){
      const H8 dn = ONES ? dcalc1(Xh, h+1, w, g)
                         : dcalc(z1, z2, Xh, h+1, w, g, s1h, s2h);
#pragma unroll
      for (int i=0;i<4;++i)
        w1o.h[i] = __hfma2(tth, __hsub2(dn.h[i], d00.h[i]), z1c.h[i]);
    }
    if (w < W_-1){
      const H8 de = ONES ? dcalc1(Xh, h, w+1, g)
                         : dcalc(z1, z2, Xh, h, w+1, g, s1h, s2h);
#pragma unroll
      for (int i=0;i<4;++i)
        w2o.h[i] = __hfma2(tth, __hsub2(de.h[i], d00.h[i]), z2c.h[i]);
    }

    st8h(zout, idx, w1o);
    st8h(zout + HWG, idx, w2o);
#pragma unroll
    for (int i=0;i<4;++i){
      const __half2 t1 = __hmul2(w1o.h[i], inv16);
      const __half2 t2 = __hmul2(w2o.h[i], inv16);
      acch1 = __hfma2(t1, t1, acch1);
      acch2 = __hfma2(t2, t2, acch2);
    }
  }
  const float2 f1 = __half22float2(acch1);
  const float2 f2 = __half22float2(acch2);
  out1 = (f1.x + f1.y) * 256.f;
  out2 = (f2.x + f2.y) * 256.f;
}

// ---------------- grid barrier + projection-scale publication ----------------
__device__ __forceinline__ void reduce_and_sync(
    unsigned target, int h, int chunkbase, float v1, float v2,
    float* __restrict__ ss, float* __restrict__ sc,
    unsigned* __restrict__ cnt, volatile unsigned* gen,
    float* sm1, float* sm2, int* elected, int tid)
{
  sm1[tid] = v1; sm2[tid] = v2;
  __syncthreads();
  for (int s = 128; s > 0; s >>= 1){
    if (tid < s){ sm1[tid] += sm1[tid+s]; sm2[tid] += sm2[tid+s]; }
    __syncthreads();
  }
  if (tid == 0){
    ss[chunkbase + h]      = sm1[0];
    ss[chunkbase + H_ + h] = sm2[0];
    __threadfence();
    *elected = (atomicAdd(cnt, 1u) == NCTA_STEP - 1u);
  }
  __syncthreads();
  if (*elected){
    __threadfence();
    float w1 = 0.f, w2 = 0.f;
    for (int hh = tid; hh < H_; hh += 256){
      w1 += sqrtf(ss[hh]       + ss[2*H_ + hh]);
      w2 += sqrtf(ss[H_ + hh]  + ss[3*H_ + hh]);
    }
    sm1[tid] = w1; sm2[tid] = w2;
    __syncthreads();
    for (int s = 128; s > 0; s >>= 1){
      if (tid < s){ sm1[tid] += sm1[tid+s]; sm2[tid] += sm2[tid+s]; }
      __syncthreads();
    }
    if (tid == 0){
      const float n1 = sm1[0], n2 = sm2[0];
      sc[0] = (n1 > 1.f) ? (1.f/n1) : 1.f;
      sc[1] = (n2 > 1.f) ? (1.f/n2) : 1.f;
      __threadfence();
      *cnt = 0u;                 // re-arm arrivals for the next step
      *gen = target;             // release
    }
  }
  if (tid == 0){
    while (*gen < target) __nanosleep(64);
  }
  __syncthreads();
  __threadfence();               // acquire side: order subsequent z reads
}

// ---------------- persistent inner loop + fused final div --------------------
// grid (2, H) = 1024 CTAs; all co-resident (8 CTAs/SM by threads, 148 SMs).
// Phase 6 (final div) adds NO new synchronization: per-CTA code after the
// last barrier, identical math to the former final_div kernel.
__global__ __launch_bounds__(256, 8)
void inner_persist(uint4* __restrict__ z_a, uint4* __restrict__ z_b,
                   const uint4* __restrict__ Xh,
                   const float4* __restrict__ Xp, float4* __restrict__ Uo,
                   float* __restrict__ ss, float* __restrict__ sc,
                   unsigned* __restrict__ cnt, unsigned* __restrict__ gen,
                   unsigned* __restrict__ cnt2)
{
  const int h   = blockIdx.y;
  const int w0  = blockIdx.x << 8;
  const int tid = threadIdx.x;
  const int chunkbase = blockIdx.x ? 2*H_ : 0;
  __shared__ float sm1[256], sm2[256];
  __shared__ int elected;
  volatile unsigned* vgen = (volatile unsigned*)gen;

  float a1, a2;
  // step 0: z == ones
  {
    const __half2 one = __float2half2_rn(1.f);
    step_body<true>(z_b, z_a, Xh, one, one, h, w0, tid, a1, a2);
    reduce_and_sync(1u, h, chunkbase, a1, a2, ss, sc, cnt, vgen,
                    sm1, sm2, &elected, tid);
  }
  // steps 1..4
#pragma unroll 1
  for (int j = 1; j < 5; ++j){
    const float s1 = sc[0], s2 = sc[1];
    const __half2 s1h = __float2half2_rn(s1);
    const __half2 s2h = __float2half2_rn(s2);
    const uint4* zi = (j & 1) ? z_a : z_b;
    uint4*       zo = (j & 1) ? z_b : z_a;
    step_body<false>(zi, zo, Xh, s1h, s2h, h, w0, tid, a1, a2);
    reduce_and_sync((unsigned)(j + 1), h, chunkbase, a1, a2, ss, sc, cnt, vgen,
                    sm1, sm2, &elected, tid);
  }
  // phase 6 (fused final_div): U = X + LMBDA * div(s .* z); z in z_a, s in sc
  {
    const float s1 = sc[0], s2 = sc[1];
    const uint4* __restrict__ z1 = z_a;
    const uint4* __restrict__ z2 = z_a + HWG;
#pragma unroll 1
    for (int p = 0; p < 8; ++p){
      const int flat = (p << 8) + tid;
      const int w  = w0 + (flat >> 3);
      const int g  = flat & 7;
      const F8 a = h8f(dz1(z1, h, w, g));
      const F8 b = h8f(dz2(z2, h, w, g));
      const int i4 = (h*W_ + w)*C4_ + 2*g;
      const float4 xp = Xp[i4], xq = Xp[i4+1];
      const float xv[8] = {xp.x,xp.y,xp.z,xp.w, xq.x,xq.y,xq.z,xq.w};
      float r[8];
#pragma unroll
      for (int i = 0; i < 8; ++i)
        r[i] = fmaf(LMBDA, fmaf(s1, a.a[i], s2*b.a[i]), xv[i]);
      Uo[i4]   = make_float4(r[0], r[1], r[2], r[3]);
      Uo[i4+1] = make_float4(r[4], r[5], r[6], r[7]);
    }
  }
  // exit: last CTA resets the generation flag for the next launch / replay
  if (tid == 0){
    const unsigned old = atomicAdd(cnt2, 1u);
    if (old == NCTA_STEP - 1u){
      *vgen = 0u;
      *cnt2 = 0u;
    }
  }
}

// ---------------- fp16 tensor-core GEMM (single-term, hi-only) ---------------
__device__ __forceinline__ void mma_f16(float (&c)[4], const uint32_t* a,
                                        const uint32_t* b){
  asm volatile(
    "mma.sync.aligned.m16n8k16.row.col.f32.f16.f16.f32 "
    "{%0,%1,%2,%3}, {%4,%5,%6,%7}, {%8,%9}, {%0,%1,%2,%3};"
    : "+f"(c[0]), "+f"(c[1]), "+f"(c[2]), "+f"(c[3])
    : "r"(a[0]), "r"(a[1]), "r"(a[2]), "r"(a[3]), "r"(b[0]), "r"(b[1]));
}

#define SAH 20                     // A smem stride (b32 units; 16 used + 4 pad)
#define SBH 20                     // B smem stride
#define SMEM_TC ((128*SAH + 64*SBH)*4)   // 15.3 KB

// out[h][m0:m0+128, 0:64] = cU*Uin + cMM*( [do_p1] Uin@N1  +  A2@Bin[h] ) + cP*Pb
// If outh != nullptr, also writes INV_LMBDA*result to the half8 buffer.
__global__ __launch_bounds__(256)
void gemm_tc(float* __restrict__ out, int out_h, __half* __restrict__ outh,
             const float* __restrict__ Uin,
             const float* __restrict__ N1,
             const float* __restrict__ A2,
             const float* __restrict__ Bin, int bin_h,
             const float* __restrict__ Pb,
             int K2, int do_p1, float cU, float cMM, float cP)
{
  extern __shared__ unsigned smemU[];
  unsigned* Ah = smemU;             // [128][SAH]  A hi, packed half2 (k pairs)
  unsigned* Bh = Ah + 128*SAH;      // [64][SBH]   B hi, transposed packed

  const int h   = blockIdx.y;
  const int m0  = blockIdx.x << 7;
  const int tid = threadIdx.x;
  const int lane = tid & 31, wid = tid >> 5;
  const int wm = wid & 3, wn = wid >> 2;      // 4 x 2 warps over (128m, 64n)
  const int gid = lane >> 2, t4 = lane & 3;

  float acc[2][4][4];
#pragma unroll
  for (int i = 0; i < 2; ++i)
#pragma unroll
    for (int j = 0; j < 4; ++j)
#pragma unroll
      for (int q = 0; q < 4; ++q) acc[i][j][q] = 0.f;

  for (int ph = 0; ph < 2; ++ph){
    const float* Ag; int lda; const float* Bg; int Kp;
    if (ph == 0){
      if (!do_p1) continue;
      Ag = Uin + (size_t)h*32768 + (size_t)m0*64; lda = 64; Bg = N1; Kp = 64;
    } else {
      Ag = A2 + (size_t)m0*K2; lda = K2; Bg = Bin + (size_t)h*bin_h; Kp = K2;
    }
    for (int k0 = 0; k0 < Kp; k0 += 32){
      __syncthreads();
      // fill A chunk 128x32: hi only, packed half2 by k-pairs
      {
        const int row0 = tid >> 3;            // 0..31
        const int k4   = (tid & 7) << 2;      // 0,4,..,28
#pragma unroll
        for (int r = 0; r < 4; ++r){
          const int row = row0 + 32*r;
          const float4 v = *(const float4*)(Ag + (size_t)row*lda + k0 + k4);
          Ah[row*SAH + (k4>>1)]     = h2u(__floats2half2_rn(v.x, v.y));
          Ah[row*SAH + (k4>>1) + 1] = h2u(__floats2half2_rn(v.z, v.w));
        }
      }
      // fill B chunk 32x64: transpose to [n][k2], hi only, packed half2
      {
        const int k2 = tid & 15;              // k-pair index 0..15
        const int n4 = (tid >> 4) << 2;       // 0,4,..,60
        const float* B0 = Bg + (size_t)(k0 + 2*k2)*64 + n4;
        const float4 va = *(const float4*)B0;        // k even row
        const float4 vb = *(const float4*)(B0 + 64); // k odd row
        const float av[4] = {va.x, va.y, va.z, va.w};
        const float bv[4] = {vb.x, vb.y, vb.z, vb.w};
#pragma unroll
        for (int j = 0; j < 4; ++j)
          Bh[(n4+j)*SBH + k2] = h2u(__floats2half2_rn(av[j], bv[j]));
      }
      __syncthreads();
#pragma unroll
      for (int kf = 0; kf < 2; ++kf){         // two k16 fragments per chunk
        const int base = kf*8;
        uint32_t ah[2][4];
#pragma unroll
        for (int fm = 0; fm < 2; ++fm){
          const int r0 = wm*32 + fm*16 + gid;
          ah[fm][0] = Ah[r0*SAH + base + t4];
          ah[fm][1] = Ah[(r0+8)*SAH + base + t4];
          ah[fm][2] = Ah[r0*SAH + base + t4 + 4];
          ah[fm][3] = Ah[(r0+8)*SAH + base + t4 + 4];
        }
        uint32_t bhv[4][2];
#pragma unroll
        for (int fn = 0; fn < 4; ++fn){
          const int n = wn*32 + fn*8 + gid;
          bhv[fn][0] = Bh[n*SBH + base + t4];
          bhv[fn][1] = Bh[n*SBH + base + t4 + 4];
        }
#pragma unroll
        for (int fm = 0; fm < 2; ++fm)
#pragma unroll
          for (int fn = 0; fn < 4; ++fn)
            mma_f16(acc[fm][fn], ah[fm], bhv[fn]);
      }
    }
  }

  // epilogue
  float* Oh = out + (size_t)h*out_h;
  __half* Ohh = outh ? (outh + (size_t)h*out_h) : nullptr;
  const float* Uh = Uin + (size_t)h*32768;
  const float* Ph = Pb  + (size_t)h*32768;
#pragma unroll
  for (int fm = 0; fm < 2; ++fm){
#pragma unroll
    for (int fn = 0; fn < 4; ++fn){
      const int r0 = m0 + wm*32 + fm*16 + gid;
      const int c0 = wn*32 + fn*8 + 2*t4;
#pragma unroll
      for (int half = 0; half < 2; ++half){
        const int r = r0 + 8*half;
        float v0 = cMM * acc[fm][fn][2*half];
        float v1 = cMM * acc[fm][fn][2*half + 1];
        if (cU != 0.f){
          const float2 u = *(const float2*)(Uh + (size_t)r*64 + c0);
          v0 += cU*u.x; v1 += cU*u.y;
        }
        if (cP != 0.f){
          const float2 pv = *(const float2*)(Ph + (size_t)r*64 + c0);
          v0 += cP*pv.x; v1 += cP*pv.y;
        }
        *(float2*)(Oh + (size_t)r*64 + c0) = make_float2(v0, v1);
        if (Ohh)
          *reinterpret_cast<__half2*>(Ohh + (size_t)r*64 + c0) =
            __floats2half2_rn(INV_LMBDA*v0, INV_LMBDA*v1);
      }
    }
  }
}

__global__ void transpose_R(float* __restrict__ Rt, const float* __restrict__ R)
{
  const int i = blockIdx.x*256 + threadIdx.x;
  if (i < W_*WM_){
    const int w = i / WM_, m = i % WM_;
    Rt[i] = R[m*W_ + w];
  }
}

__global__ void compute_M1(float* __restrict__ M1, const float* __restrict__ B,
                           const float* __restrict__ Bt)
{
  const int i = blockIdx.x*256 + threadIdx.x;
  if (i < C_*C_){
    const int m = i >> 6, n = i & 63;
    float s = 0.f;
#pragma unroll 8
    for (int k = 0; k < C_; ++k) s += B[m*C_ + k]*Bt[k*C_ + n];
    M1[i] = s;
  }
}

// ---------------- driver ----------------------------------------------------
extern "C" void kernel_launch(void* const* d_in, const int* in_sizes, int n_in,
                              void* d_out, int out_size)
{
  const float* Y_H = (const float*)d_in[0];
  const float* Y_M = (const float*)d_in[1];
  const float* B   = (const float*)d_in[2];
  const float* B_t = (const float*)d_in[3];
  const float* R   = (const float*)d_in[4];
  float* U = (float*)d_out;

  uint4 *zA, *zB, *Xh, *Ph;
  float4 *X, *P;
  float *T, *M1, *Rt, *ss, *sc;
  unsigned *cnt, *gen, *cnt2;
  cudaGetSymbolAddress((void**)&zA,   g_zA);
  cudaGetSymbolAddress((void**)&zB,   g_zB);
  cudaGetSymbolAddress((void**)&X,    g_X);
  cudaGetSymbolAddress((void**)&P,    g_P);
  cudaGetSymbolAddress((void**)&Xh,   g_Xh);
  cudaGetSymbolAddress((void**)&Ph,   g_Ph);
  cudaGetSymbolAddress((void**)&T,    g_T);
  cudaGetSymbolAddress((void**)&M1,   g_M1);
  cudaGetSymbolAddress((void**)&Rt,   g_Rt);
  cudaGetSymbolAddress((void**)&ss,   g_ss);
  cudaGetSymbolAddress((void**)&sc,   g_sc);
  cudaGetSymbolAddress((void**)&cnt,  g_cnt);
  cudaGetSymbolAddress((void**)&gen,  g_gen);
  cudaGetSymbolAddress((void**)&cnt2, g_cnt2);

  const dim3 blk2(256);
  const dim3 grd2(2, H_);

  transpose_R<<<(W_*WM_ + 255)/256, 256>>>(Rt, R);
  compute_M1 <<<(C_*C_ + 255)/256, 256>>>(M1, B, B_t);
  // P = LMBDA*(Y_H@B_t + Rt@Y_M), plus Ph = 10*P in half
  gemm_tc<<<dim3(4, H_), 256, SMEM_TC>>>((float*)P, 32768, (__half*)Ph,
                                         Y_H, B_t, Rt, Y_M, WM_*C_,
                                         (const float*)P,
                                         WM_, 1, 0.f, LMBDA, 0.f);

  for (int it = 0; it < 5; ++it){
    const uint4* Xhp;
    const float4* Xp;
    if (it == 0){
      Xhp = Ph; Xp = P;                         // U = 0 -> X = P exactly
    } else {
      // T[h] = R @ U[h]
      gemm_tc<<<dim3(1, H_), 256, SMEM_TC>>>(T, WM_*C_, (__half*)nullptr,
                                             U, M1, R, U, W_*C_,
                                             (const float*)P,
                                             W_, 0, 0.f, 1.f, 0.f);
      // X = U - LMBDA*(U@M1 + Rt@T) + P, plus Xh = 10*X in half
      gemm_tc<<<dim3(4, H_), 256, SMEM_TC>>>((float*)X, 32768, (__half*)Xh,
                                             U, M1, Rt, T, WM_*C_,
                                             (const float*)P,
                                             WM_, 1, 1.f, -LMBDA, 1.f);
      Xhp = Xh; Xp = X;
    }
    // 5 dual iterations + fused final div in ONE persistent launch
    inner_persist<<<grd2, blk2>>>(zA, zB, (const uint4*)Xhp,
                                  Xp, (float4*)U, ss, sc, cnt, gen, cnt2);
  }
}